// round 12
// baseline (speedup 1.0000x reference)
#include <cuda_runtime.h>
#include <cuda_bf16.h>
#include <cuda_fp16.h>
#include <mma.h>
#include <cstdint>

using namespace nvcuda;

// ---------------------------------------------------------------------------
// AdjGCN: 3-layer GCN forward.
//  - CSR built on a forked stream (int2 edge payload).
//  - H stored fp16; aggregation accumulates fp32.
//  - Layer fusion: agg(layer i) feeds gemm(layer i+1) through SMEM within one
//    kernel (block = 64 nodes). GEMMs: wmma bf16x3 (fp32-accurate).
// Pipeline: gemmL1 || CSR -> fused aggL1+gemmL2 -> fused aggL2+gemm40 -> lsm
// ---------------------------------------------------------------------------

#define MAXN 100000
#define MAXNP 100096
#define MAXE 1600000
#define DH   128
#define DO   40
#define LDX  136
#define LDW  136
#define LDS  132

__device__ float         g_bufA[(size_t)MAXNP * DH];   // fp16 H (layer1), then H40
__device__ float         g_bufB[(size_t)MAXNP * DH];   // fp16 H (layer2)
__device__ int           g_idx64;
__device__ int           g_rowptr[MAXN + 1];
__device__ int           g_deg[MAXN];
__device__ int           g_fill[MAXN];
__device__ int2          g_epack[MAXE];
__device__ int           g_partials[128];
__device__ __nv_bfloat16 g_w1hi[128 * 128];
__device__ __nv_bfloat16 g_w1lo[128 * 128];
__device__ __nv_bfloat16 g_w2hi[128 * 128];
__device__ __nv_bfloat16 g_w2lo[128 * 128];

// ------------------------------ CSR build ---------------------------------
__global__ void deg_zero_kernel(int* __restrict__ deg, int n,
                                const void* ei, int n_nodes) {
    int i = blockIdx.x * blockDim.x + threadIdx.x;
    if (i < n) deg[i] = 0;
    if (blockIdx.x == 0 && threadIdx.x == 0) {
        const long long* p = (const long long*)ei;
        int ok64 = 1;
        for (int k = 0; k < 32; k++) {
            long long v = p[k];
            if (v < 0 || v >= n_nodes) { ok64 = 0; break; }
        }
        g_idx64 = ok64;
    }
}

__global__ void deg_count_kernel(const void* __restrict__ ei, int ne,
                                 int* __restrict__ deg) {
    int e = (blockIdx.x * blockDim.x + threadIdx.x) * 2;
    if (e >= ne) return;
    int d0, d1 = -1;
    if (g_idx64) {
        const long long* p = (const long long*)ei + ne;
        if (e + 1 < ne) {
            longlong2 v = *(const longlong2*)(p + e);
            d0 = (int)v.x; d1 = (int)v.y;
        } else d0 = (int)p[e];
    } else {
        const int* p = (const int*)ei + ne;
        if (e + 1 < ne) {
            int2 v = *(const int2*)(p + e);
            d0 = v.x; d1 = v.y;
        } else d0 = p[e];
    }
    atomicAdd(&deg[d0], 1);
    if (d1 >= 0) atomicAdd(&deg[d1], 1);
}

__global__ void scan_block_kernel(const int* __restrict__ deg,
                                  int* __restrict__ rowptr,
                                  int* __restrict__ partials, int n) {
    __shared__ int sm[1024];
    const int tid = threadIdx.x;
    int i = blockIdx.x * 1024 + tid;
    int v = (i < n) ? deg[i] : 0;
    sm[tid] = v;
    __syncthreads();
#pragma unroll
    for (int o = 1; o < 1024; o <<= 1) {
        int t = (tid >= o) ? sm[tid - o] : 0;
        __syncthreads();
        sm[tid] += t;
        __syncthreads();
    }
    if (i < n) rowptr[i] = sm[tid] - v;
    if (tid == 1023) partials[blockIdx.x] = sm[1023];
}

__global__ void scan_partials_kernel(int* __restrict__ partials, int nb) {
    __shared__ int sm[128];
    const int tid = threadIdx.x;
    int v = (tid < nb) ? partials[tid] : 0;
    sm[tid] = v;
    __syncthreads();
#pragma unroll
    for (int o = 1; o < 128; o <<= 1) {
        int t = (tid >= o) ? sm[tid - o] : 0;
        __syncthreads();
        sm[tid] += t;
        __syncthreads();
    }
    if (tid < nb) partials[tid] = sm[tid] - v;
}

__global__ void scan_add_kernel(int* __restrict__ rowptr,
                                const int* __restrict__ partials,
                                int* __restrict__ fill, int n, int ne) {
    int i = blockIdx.x * blockDim.x + threadIdx.x;
    if (i < n) {
        int v = rowptr[i] + partials[i >> 10];
        rowptr[i] = v;
        fill[i] = v;
    }
    if (i == 0) rowptr[n] = ne;
}

__global__ void csr_fill_kernel(const void* __restrict__ ei,
                                const float* __restrict__ ew, int ne,
                                int* __restrict__ fill,
                                int2* __restrict__ epack) {
    int e = (blockIdx.x * blockDim.x + threadIdx.x) * 2;
    if (e >= ne) return;
    int s0, d0, s1 = -1, d1 = -1;
    float w0, w1 = 0.f;
    if (g_idx64) {
        const long long* ps = (const long long*)ei;
        const long long* pd = ps + ne;
        if (e + 1 < ne) {
            longlong2 sv = *(const longlong2*)(ps + e);
            longlong2 dv = *(const longlong2*)(pd + e);
            float2 wv = *(const float2*)(ew + e);
            s0 = (int)sv.x; s1 = (int)sv.y;
            d0 = (int)dv.x; d1 = (int)dv.y;
            w0 = wv.x; w1 = wv.y;
        } else { s0 = (int)ps[e]; d0 = (int)pd[e]; w0 = ew[e]; }
    } else {
        const int* ps = (const int*)ei;
        const int* pd = ps + ne;
        if (e + 1 < ne) {
            int2 sv = *(const int2*)(ps + e);
            int2 dv = *(const int2*)(pd + e);
            float2 wv = *(const float2*)(ew + e);
            s0 = sv.x; s1 = sv.y; d0 = dv.x; d1 = dv.y;
            w0 = wv.x; w1 = wv.y;
        } else { s0 = ps[e]; d0 = pd[e]; w0 = ew[e]; }
    }
    int p0 = atomicAdd(&fill[d0], 1);
    epack[p0] = make_int2(s0, __float_as_int(w0));
    if (s1 >= 0) {
        int p1 = atomicAdd(&fill[d1], 1);
        epack[p1] = make_int2(s1, __float_as_int(w1));
    }
}

// ------------- W prep: fp32 -> bf16 hi/lo for W1 and W2, fused -------------
__global__ void prep_w2_kernel(const float* __restrict__ Wa,
                               __nv_bfloat16* __restrict__ ahi,
                               __nv_bfloat16* __restrict__ alo,
                               const float* __restrict__ Wb,
                               __nv_bfloat16* __restrict__ bhi,
                               __nv_bfloat16* __restrict__ blo) {
    int i = blockIdx.x * blockDim.x + threadIdx.x;
    if (i < 128 * 128) {
        float w = Wa[i];
        __nv_bfloat16 h = __float2bfloat16_rn(w);
        ahi[i] = h;
        alo[i] = __float2bfloat16_rn(w - __bfloat162float(h));
    } else if (i < 2 * 128 * 128) {
        int k = i - 128 * 128;
        float w = Wb[k];
        __nv_bfloat16 h = __float2bfloat16_rn(w);
        bhi[k] = h;
        blo[k] = __float2bfloat16_rn(w - __bfloat162float(h));
    }
}

// ------------------ shared helpers for bf16 hi/lo packing ------------------
__device__ __forceinline__ uint64_t pack4_hi(float a, float b, float c, float d) {
    __nv_bfloat162 p0 = __floats2bfloat162_rn(a, b);
    __nv_bfloat162 p1 = __floats2bfloat162_rn(c, d);
    return (uint64_t)(*(uint32_t*)&p0) | ((uint64_t)(*(uint32_t*)&p1) << 32);
}
__device__ __forceinline__ uint64_t pack4_lo(float a, float b, float c, float d) {
    float ah = __bfloat162float(__float2bfloat16_rn(a));
    float bh = __bfloat162float(__float2bfloat16_rn(b));
    float ch = __bfloat162float(__float2bfloat16_rn(c));
    float dh = __bfloat162float(__float2bfloat16_rn(d));
    __nv_bfloat162 p0 = __floats2bfloat162_rn(a - ah, b - bh);
    __nv_bfloat162 p1 = __floats2bfloat162_rn(c - ch, d - dh);
    return (uint64_t)(*(uint32_t*)&p0) | ((uint64_t)(*(uint32_t*)&p1) << 32);
}

// --------------- wmma bf16x3 mainloop + fp16 epilogue (macro body) ---------
__device__ __forceinline__ void wmma_mainloop_epilogue(
    char* smem, __nv_bfloat16* xhi, __nv_bfloat16* xlo,
    __nv_bfloat16* wh, __nv_bfloat16* wl,
    __half* __restrict__ Yh, int row0, int tid) {
    const int w  = tid >> 5;
    const int wr = w >> 2;
    const int wc = w & 3;

    wmma::fragment<wmma::accumulator, 16, 16, 16, float> acc[2][2];
#pragma unroll
    for (int i = 0; i < 2; i++)
#pragma unroll
        for (int j = 0; j < 2; j++) wmma::fill_fragment(acc[i][j], 0.f);

#pragma unroll
    for (int ks = 0; ks < 8; ks++) {
        const int k0 = ks * 16;
        wmma::fragment<wmma::matrix_a, 16, 16, 16, __nv_bfloat16,
                       wmma::row_major> ah[2], al[2];
        wmma::fragment<wmma::matrix_b, 16, 16, 16, __nv_bfloat16,
                       wmma::row_major> bh[2], bl[2];
#pragma unroll
        for (int i = 0; i < 2; i++) {
            wmma::load_matrix_sync(ah[i], &xhi[(wr * 32 + i * 16) * LDX + k0], LDX);
            wmma::load_matrix_sync(al[i], &xlo[(wr * 32 + i * 16) * LDX + k0], LDX);
        }
#pragma unroll
        for (int j = 0; j < 2; j++) {
            wmma::load_matrix_sync(bh[j], &wh[k0 * LDW + wc * 32 + j * 16], LDW);
            wmma::load_matrix_sync(bl[j], &wl[k0 * LDW + wc * 32 + j * 16], LDW);
        }
#pragma unroll
        for (int i = 0; i < 2; i++)
#pragma unroll
            for (int j = 0; j < 2; j++) {
                wmma::mma_sync(acc[i][j], ah[i], bh[j], acc[i][j]);
                wmma::mma_sync(acc[i][j], ah[i], bl[j], acc[i][j]);
                wmma::mma_sync(acc[i][j], al[i], bh[j], acc[i][j]);
            }
    }

    __syncthreads();
    float* stage = (float*)smem;
#pragma unroll
    for (int i = 0; i < 2; i++)
#pragma unroll
        for (int j = 0; j < 2; j++) {
            wmma::store_matrix_sync(&stage[(wr * 32 + i * 16) * LDS
                                           + wc * 32 + j * 16],
                                    acc[i][j], LDS, wmma::mem_row_major);
        }
    __syncthreads();
    __half2* Y2 = (__half2*)Yh;
#pragma unroll
    for (int i = tid; i < 64 * 64; i += 256) {
        int r = i >> 6, c2 = i & 63;
        float a = stage[r * LDS + 2 * c2];
        float b = stage[r * LDS + 2 * c2 + 1];
        Y2[(size_t)(row0 + r) * 64 + c2] = __floats2half2_rn(a, b);
    }
}

// ---------- layer-1 GEMM: fp32 X -> bf16x3 wmma -> fp16 H ------------------
__global__ void gemm128_tc_kernel(const float* __restrict__ X,
                                  const __nv_bfloat16* __restrict__ Whi,
                                  const __nv_bfloat16* __restrict__ Wlo,
                                  __half* __restrict__ Yh, int nrows) {
    extern __shared__ char smem[];
    __nv_bfloat16* xhi = (__nv_bfloat16*)smem;
    __nv_bfloat16* xlo = xhi + 64 * LDX;
    __nv_bfloat16* wh  = xlo + 64 * LDX;
    __nv_bfloat16* wl  = wh + 128 * LDW;
    const int tid = threadIdx.x;
    const int row0 = blockIdx.x * 64;

    {
        const float4* X4 = (const float4*)X;
#pragma unroll
        for (int i = tid; i < 64 * 32; i += 256) {
            int r = i >> 5, kq = i & 31;
            float4 v = (row0 + r < nrows)
                           ? X4[(size_t)(row0 + r) * 32 + kq]
                           : make_float4(0.f, 0.f, 0.f, 0.f);
            *(uint64_t*)&xhi[r * LDX + kq * 4] = pack4_hi(v.x, v.y, v.z, v.w);
            *(uint64_t*)&xlo[r * LDX + kq * 4] = pack4_lo(v.x, v.y, v.z, v.w);
        }
    }
    {
        const int4* h4 = (const int4*)Whi;
        const int4* l4 = (const int4*)Wlo;
#pragma unroll
        for (int i = tid; i < 2048; i += 256) {
            int k = i >> 4, seg = i & 15;
            *(int4*)&wh[k * LDW + seg * 8] = h4[i];
            *(int4*)&wl[k * LDW + seg * 8] = l4[i];
        }
    }
    __syncthreads();
    wmma_mainloop_epilogue(smem, xhi, xlo, wh, wl, Yh, row0, tid);
}

// ------ FUSED: agg128 (fp16 gather, bias+relu) -> gemm128 (bf16x3) ---------
// Block = 64 nodes, 256 threads. Warp w aggregates nodes row0+8w..+7 into
// the X tile (bf16 hi/lo) directly, then the block runs the wmma mainloop.
__global__ void agg_gemm128_kernel(const int* __restrict__ rowptr,
                                   const int2* __restrict__ epack,
                                   const __half* __restrict__ Hin,
                                   const float* __restrict__ bias,
                                   const __nv_bfloat16* __restrict__ Whi,
                                   const __nv_bfloat16* __restrict__ Wlo,
                                   __half* __restrict__ Yh, int n) {
    extern __shared__ char smem[];
    __nv_bfloat16* xhi = (__nv_bfloat16*)smem;
    __nv_bfloat16* xlo = xhi + 64 * LDX;
    __nv_bfloat16* wh  = xlo + 64 * LDX;
    __nv_bfloat16* wl  = wh + 128 * LDW;
    const int tid = threadIdx.x;
    const int lane = tid & 31;
    const int wid = tid >> 5;
    const int row0 = blockIdx.x * 64;

    // W blobs -> smem
    {
        const int4* h4 = (const int4*)Whi;
        const int4* l4 = (const int4*)Wlo;
#pragma unroll
        for (int i = tid; i < 2048; i += 256) {
            int k = i >> 4, seg = i & 15;
            *(int4*)&wh[k * LDW + seg * 8] = h4[i];
            *(int4*)&wl[k * LDW + seg * 8] = l4[i];
        }
    }

    // Aggregate 8 nodes per warp; write bf16 hi/lo rows into the X tile.
    float4 b4 = ((const float4*)bias)[lane];
#pragma unroll
    for (int k = 0; k < 8; k++) {
        int r = wid * 8 + k;
        int node = row0 + r;
        float4 acc = make_float4(0.f, 0.f, 0.f, 0.f);
        if (node < n) {
            int beg = rowptr[node];
            int end = rowptr[node + 1];
            int j = beg;
            for (; j + 3 < end; j += 4) {
                int2 e0 = epack[j];     int2 e1 = epack[j + 1];
                int2 e2 = epack[j + 2]; int2 e3 = epack[j + 3];
                float w0 = __int_as_float(e0.y), w1 = __int_as_float(e1.y);
                float w2 = __int_as_float(e2.y), w3 = __int_as_float(e3.y);
                uint2 u0 = ((const uint2*)(Hin + (size_t)e0.x * 128))[lane];
                uint2 u1 = ((const uint2*)(Hin + (size_t)e1.x * 128))[lane];
                uint2 u2 = ((const uint2*)(Hin + (size_t)e2.x * 128))[lane];
                uint2 u3 = ((const uint2*)(Hin + (size_t)e3.x * 128))[lane];
                float2 a0 = __half22float2(*(__half2*)&u0.x);
                float2 c0 = __half22float2(*(__half2*)&u0.y);
                float2 a1 = __half22float2(*(__half2*)&u1.x);
                float2 c1 = __half22float2(*(__half2*)&u1.y);
                float2 a2 = __half22float2(*(__half2*)&u2.x);
                float2 c2 = __half22float2(*(__half2*)&u2.y);
                float2 a3 = __half22float2(*(__half2*)&u3.x);
                float2 c3 = __half22float2(*(__half2*)&u3.y);
                acc.x += a0.x * w0 + a1.x * w1 + a2.x * w2 + a3.x * w3;
                acc.y += a0.y * w0 + a1.y * w1 + a2.y * w2 + a3.y * w3;
                acc.z += c0.x * w0 + c1.x * w1 + c2.x * w2 + c3.x * w3;
                acc.w += c0.y * w0 + c1.y * w1 + c2.y * w2 + c3.y * w3;
            }
            for (; j < end; j++) {
                int2 e = epack[j];
                float w = __int_as_float(e.y);
                uint2 u = ((const uint2*)(Hin + (size_t)e.x * 128))[lane];
                float2 a = __half22float2(*(__half2*)&u.x);
                float2 c = __half22float2(*(__half2*)&u.y);
                acc.x += a.x * w; acc.y += a.y * w;
                acc.z += c.x * w; acc.w += c.y * w;
            }
            acc.x = fmaxf(acc.x + b4.x, 0.f);
            acc.y = fmaxf(acc.y + b4.y, 0.f);
            acc.z = fmaxf(acc.z + b4.z, 0.f);
            acc.w = fmaxf(acc.w + b4.w, 0.f);
        }
        *(uint64_t*)&xhi[r * LDX + lane * 4] = pack4_hi(acc.x, acc.y, acc.z, acc.w);
        *(uint64_t*)&xlo[r * LDX + lane * 4] = pack4_lo(acc.x, acc.y, acc.z, acc.w);
    }
    __syncthreads();
    wmma_mainloop_epilogue(smem, xhi, xlo, wh, wl, Yh, row0, tid);
}

// ------ FUSED: agg128 (fp16 gather, bias+relu) -> gemm40 (SIMT) ------------
// 320 threads; agg fills fp32 X tile in smem, then D_OUT=40 SIMT gemm.
__global__ void agg_gemm40_kernel(const int* __restrict__ rowptr,
                                  const int2* __restrict__ epack,
                                  const __half* __restrict__ Hin,
                                  const float* __restrict__ bias,
                                  const float* __restrict__ W,
                                  __half* __restrict__ Yh, int n) {
    extern __shared__ float smf[];
    float* Ws = smf;                 // 128*40
    float* Xs = smf + 128 * DO;      // 64*128
    const int tid = threadIdx.x;
    const int lane = tid & 31;
    const int wid = tid >> 5;        // 0..9
    const int row0 = blockIdx.x * 64;

    for (int i = tid; i < 128 * DO; i += 320) Ws[i] = W[i];

    float4 b4 = ((const float4*)bias)[lane];
    for (int r = wid; r < 64; r += 10) {
        int node = row0 + r;
        float4 acc = make_float4(0.f, 0.f, 0.f, 0.f);
        if (node < n) {
            int beg = rowptr[node];
            int end = rowptr[node + 1];
            int j = beg;
            for (; j + 3 < end; j += 4) {
                int2 e0 = epack[j];     int2 e1 = epack[j + 1];
                int2 e2 = epack[j + 2]; int2 e3 = epack[j + 3];
                float w0 = __int_as_float(e0.y), w1 = __int_as_float(e1.y);
                float w2 = __int_as_float(e2.y), w3 = __int_as_float(e3.y);
                uint2 u0 = ((const uint2*)(Hin + (size_t)e0.x * 128))[lane];
                uint2 u1 = ((const uint2*)(Hin + (size_t)e1.x * 128))[lane];
                uint2 u2 = ((const uint2*)(Hin + (size_t)e2.x * 128))[lane];
                uint2 u3 = ((const uint2*)(Hin + (size_t)e3.x * 128))[lane];
                float2 a0 = __half22float2(*(__half2*)&u0.x);
                float2 c0 = __half22float2(*(__half2*)&u0.y);
                float2 a1 = __half22float2(*(__half2*)&u1.x);
                float2 c1 = __half22float2(*(__half2*)&u1.y);
                float2 a2 = __half22float2(*(__half2*)&u2.x);
                float2 c2 = __half22float2(*(__half2*)&u2.y);
                float2 a3 = __half22float2(*(__half2*)&u3.x);
                float2 c3 = __half22float2(*(__half2*)&u3.y);
                acc.x += a0.x * w0 + a1.x * w1 + a2.x * w2 + a3.x * w3;
                acc.y += a0.y * w0 + a1.y * w1 + a2.y * w2 + a3.y * w3;
                acc.z += c0.x * w0 + c1.x * w1 + c2.x * w2 + c3.x * w3;
                acc.w += c0.y * w0 + c1.y * w1 + c2.y * w2 + c3.y * w3;
            }
            for (; j < end; j++) {
                int2 e = epack[j];
                float w = __int_as_float(e.y);
                uint2 u = ((const uint2*)(Hin + (size_t)e.x * 128))[lane];
                float2 a = __half22float2(*(__half2*)&u.x);
                float2 c = __half22float2(*(__half2*)&u.y);
                acc.x += a.x * w; acc.y += a.y * w;
                acc.z += c.x * w; acc.w += c.y * w;
            }
            acc.x = fmaxf(acc.x + b4.x, 0.f);
            acc.y = fmaxf(acc.y + b4.y, 0.f);
            acc.z = fmaxf(acc.z + b4.z, 0.f);
            acc.w = fmaxf(acc.w + b4.w, 0.f);
        }
        *(float4*)&Xs[r * 128 + lane * 4] = acc;
    }
    __syncthreads();

    const int c  = tid % DO;
    const int rg = tid / DO;      // 0..7
    float acc[8];
#pragma unroll
    for (int r = 0; r < 8; r++) acc[r] = 0.f;
    const float4* xb4 = (const float4*)(Xs + rg * 8 * 128);

#pragma unroll 4
    for (int k4 = 0; k4 < 32; k4++) {
        float w0 = Ws[(4 * k4 + 0) * DO + c];
        float w1 = Ws[(4 * k4 + 1) * DO + c];
        float w2 = Ws[(4 * k4 + 2) * DO + c];
        float w3 = Ws[(4 * k4 + 3) * DO + c];
#pragma unroll
        for (int r = 0; r < 8; r++) {
            float4 xv = xb4[r * 32 + k4];
            acc[r] += xv.x * w0 + xv.y * w1 + xv.z * w2 + xv.w * w3;
        }
    }
#pragma unroll
    for (int r = 0; r < 8; r++) {
        int gr = row0 + rg * 8 + r;
        if (gr < MAXNP) Yh[(size_t)gr * DO + c] = __float2half_rn(acc[r]);
    }
}

// ---------------- final: agg40 (fp16 H) + bias + log_softmax ----------------
__global__ void agg40_lsm_kernel(const int* __restrict__ rowptr,
                                 const int2* __restrict__ epack,
                                 const __half* __restrict__ H,
                                 const float* __restrict__ b,
                                 float* __restrict__ out, int n) {
    int node = blockIdx.x * 8 + (threadIdx.x >> 5);
    if (node >= n) return;
    const int lane = threadIdx.x & 31;
    int beg = rowptr[node];
    int end = rowptr[node + 1];

    float a0 = 0.f, a1 = 0.f;
    int j = beg;
    for (; j + 1 < end; j += 2) {
        int2 e0 = epack[j]; int2 e1 = epack[j + 1];
        float w0 = __int_as_float(e0.y), w1 = __int_as_float(e1.y);
        const __half* h0 = H + (size_t)e0.x * DO;
        const __half* h1 = H + (size_t)e1.x * DO;
        a0 += __half2float(h0[lane]) * w0 + __half2float(h1[lane]) * w1;
        if (lane < 8)
            a1 += __half2float(h0[32 + lane]) * w0
                + __half2float(h1[32 + lane]) * w1;
    }
    if (j < end) {
        int2 e = epack[j];
        float w = __int_as_float(e.y);
        const __half* hs = H + (size_t)e.x * DO;
        a0 += __half2float(hs[lane]) * w;
        if (lane < 8) a1 += __half2float(hs[32 + lane]) * w;
    }

    float v0 = a0 + b[lane];
    float v1 = (lane < 8) ? (a1 + b[32 + lane]) : -1e30f;

    float m = fmaxf(v0, v1);
#pragma unroll
    for (int o = 16; o; o >>= 1) m = fmaxf(m, __shfl_xor_sync(0xffffffffu, m, o));

    float sum = __expf(v0 - m) + ((lane < 8) ? __expf(v1 - m) : 0.f);
#pragma unroll
    for (int o = 16; o; o >>= 1) sum += __shfl_xor_sync(0xffffffffu, sum, o);

    float lse = m + __logf(sum);
    out[(size_t)node * DO + lane] = v0 - lse;
    if (lane < 8) out[(size_t)node * DO + 32 + lane] = v1 - lse;
}

// ---------------------------------------------------------------------------
extern "C" void kernel_launch(void* const* d_in, const int* in_sizes, int n_in,
                              void* d_out, int out_size) {
    const float* x  = (const float*)d_in[0];
    const void*  ei = d_in[1];
    const float* ew = (const float*)d_in[2];
    const float* W1 = (const float*)d_in[3];
    const float* b1 = (const float*)d_in[4];
    const float* W2 = (const float*)d_in[5];
    const float* b2 = (const float*)d_in[6];
    const float* W3 = (const float*)d_in[7];
    const float* b3 = (const float*)d_in[8];
    float* out = (float*)d_out;

    const int n  = in_sizes[0] / DH;
    int ne = in_sizes[1] / 2;
    if (ne > MAXE) ne = MAXE;
    (void)n_in; (void)out_size;

    float *A, *B;
    int *rowptr, *deg, *fill, *partials;
    int2* epack;
    __nv_bfloat16 *w1hi, *w1lo, *w2hi, *w2lo;
    cudaGetSymbolAddress((void**)&A, g_bufA);
    cudaGetSymbolAddress((void**)&B, g_bufB);
    cudaGetSymbolAddress((void**)&rowptr, g_rowptr);
    cudaGetSymbolAddress((void**)&deg, g_deg);
    cudaGetSymbolAddress((void**)&fill, g_fill);
    cudaGetSymbolAddress((void**)&epack, g_epack);
    cudaGetSymbolAddress((void**)&partials, g_partials);
    cudaGetSymbolAddress((void**)&w1hi, g_w1hi);
    cudaGetSymbolAddress((void**)&w1lo, g_w1lo);
    cudaGetSymbolAddress((void**)&w2hi, g_w2hi);
    cudaGetSymbolAddress((void**)&w2lo, g_w2lo);

    __half* Ah  = (__half*)A;     // layer-1 H, later reused for H40
    __half* Bh  = (__half*)B;     // layer-2 H

    const int SMEM_TC = (2 * 64 * LDX + 2 * 128 * LDW) * (int)sizeof(__nv_bfloat16);
    const int SMEM40  = (128 * DO + 64 * 128) * (int)sizeof(float);
    cudaFuncSetAttribute(gemm128_tc_kernel,
                         cudaFuncAttributeMaxDynamicSharedMemorySize, SMEM_TC);
    cudaFuncSetAttribute(agg_gemm128_kernel,
                         cudaFuncAttributeMaxDynamicSharedMemorySize, SMEM_TC);
    cudaFuncSetAttribute(agg_gemm40_kernel,
                         cudaFuncAttributeMaxDynamicSharedMemorySize, SMEM40);

    const int tcBlocks       = (n + 63) / 64;
    const int nodeWarpBlocks = (n + 7) / 8;
    const int scanBlocks     = (n + 1023) / 1024;
    const int edge2Blocks    = ((ne + 1) / 2 + 255) / 256;

    static cudaStream_t s2 = nullptr;
    static cudaEvent_t evFork = nullptr, evJoin = nullptr;
    if (s2 == nullptr) {
        cudaStreamCreateWithFlags(&s2, cudaStreamNonBlocking);
        cudaEventCreateWithFlags(&evFork, cudaEventDisableTiming);
        cudaEventCreateWithFlags(&evJoin, cudaEventDisableTiming);
    }

    // ---- fork: CSR build on side stream ----
    cudaEventRecord(evFork, 0);
    cudaStreamWaitEvent(s2, evFork, 0);
    deg_zero_kernel<<<(n + 255) / 256, 256, 0, s2>>>(deg, n, ei, n);
    deg_count_kernel<<<edge2Blocks, 256, 0, s2>>>(ei, ne, deg);
    scan_block_kernel<<<scanBlocks, 1024, 0, s2>>>(deg, rowptr, partials, n);
    scan_partials_kernel<<<1, 128, 0, s2>>>(partials, scanBlocks);
    scan_add_kernel<<<(n + 255) / 256, 256, 0, s2>>>(rowptr, partials, fill, n, ne);
    csr_fill_kernel<<<edge2Blocks, 256, 0, s2>>>(ei, ew, ne, fill, epack);
    cudaEventRecord(evJoin, s2);

    // ---- main: W prep + layer-1 GEMM overlap the CSR build ----
    prep_w2_kernel<<<128, 256>>>(W1, w1hi, w1lo, W2, w2hi, w2lo);
    gemm128_tc_kernel<<<tcBlocks, 256, SMEM_TC>>>(x, w1hi, w1lo, Ah, n);

    // ---- join ----
    cudaStreamWaitEvent(0, evJoin, 0);

    // ---- fused layers ----
    agg_gemm128_kernel<<<tcBlocks, 256, SMEM_TC>>>(rowptr, epack, Ah, b1,
                                                   w2hi, w2lo, Bh, n);
    agg_gemm40_kernel<<<tcBlocks, 320, SMEM40>>>(rowptr, epack, Bh, b2,
                                                 W3, Ah, n);
    agg40_lsm_kernel<<<nodeWarpBlocks, 256>>>(rowptr, epack, Ah, b3, out, n);
}

// round 13
// speedup vs baseline: 1.1595x; 1.1595x over previous
#include <cuda_runtime.h>
#include <cuda_bf16.h>
#include <cuda_fp16.h>
#include <mma.h>
#include <cstdint>

using namespace nvcuda;

// ---------------------------------------------------------------------------
// AdjGCN: 3-layer GCN forward.  (R11 topology restored; agg128 unroll-8.)
//  - CSR-gather aggregation; CSR built on a forked stream; int2 edge payload.
//  - 128x128 GEMMs on wmma (HMMA), bf16x3 split, fp32 accumulate.
//  - H stored fp16; aggregation accumulates fp32, outputs fp32.
// ---------------------------------------------------------------------------

#define MAXN 100000
#define MAXNP 100096
#define MAXE 1600000
#define DH   128
#define DO   40
#define LDX  136
#define LDW  136
#define LDS  132

__device__ float         g_bufA[(size_t)MAXNP * DH];   // fp16 H (reused)
__device__ float         g_bufB[(size_t)MAXNP * DH];   // fp32 agg outputs
__device__ int           g_idx64;
__device__ int           g_rowptr[MAXN + 1];
__device__ int           g_deg[MAXN];
__device__ int           g_fill[MAXN];
__device__ int2          g_epack[MAXE];
__device__ int           g_partials[128];
__device__ __nv_bfloat16 g_w1hi[128 * 128];
__device__ __nv_bfloat16 g_w1lo[128 * 128];
__device__ __nv_bfloat16 g_w2hi[128 * 128];
__device__ __nv_bfloat16 g_w2lo[128 * 128];

// ------------------------------ CSR build ---------------------------------
__global__ void deg_zero_kernel(int* __restrict__ deg, int n,
                                const void* ei, int n_nodes) {
    int i = blockIdx.x * blockDim.x + threadIdx.x;
    if (i < n) deg[i] = 0;
    if (blockIdx.x == 0 && threadIdx.x == 0) {
        const long long* p = (const long long*)ei;
        int ok64 = 1;
        for (int k = 0; k < 32; k++) {
            long long v = p[k];
            if (v < 0 || v >= n_nodes) { ok64 = 0; break; }
        }
        g_idx64 = ok64;
    }
}

__global__ void deg_count_kernel(const void* __restrict__ ei, int ne,
                                 int* __restrict__ deg) {
    int e = (blockIdx.x * blockDim.x + threadIdx.x) * 2;
    if (e >= ne) return;
    int d0, d1 = -1;
    if (g_idx64) {
        const long long* p = (const long long*)ei + ne;
        if (e + 1 < ne) {
            longlong2 v = *(const longlong2*)(p + e);
            d0 = (int)v.x; d1 = (int)v.y;
        } else d0 = (int)p[e];
    } else {
        const int* p = (const int*)ei + ne;
        if (e + 1 < ne) {
            int2 v = *(const int2*)(p + e);
            d0 = v.x; d1 = v.y;
        } else d0 = p[e];
    }
    atomicAdd(&deg[d0], 1);
    if (d1 >= 0) atomicAdd(&deg[d1], 1);
}

__global__ void scan_block_kernel(const int* __restrict__ deg,
                                  int* __restrict__ rowptr,
                                  int* __restrict__ partials, int n) {
    __shared__ int sm[1024];
    const int tid = threadIdx.x;
    int i = blockIdx.x * 1024 + tid;
    int v = (i < n) ? deg[i] : 0;
    sm[tid] = v;
    __syncthreads();
#pragma unroll
    for (int o = 1; o < 1024; o <<= 1) {
        int t = (tid >= o) ? sm[tid - o] : 0;
        __syncthreads();
        sm[tid] += t;
        __syncthreads();
    }
    if (i < n) rowptr[i] = sm[tid] - v;
    if (tid == 1023) partials[blockIdx.x] = sm[1023];
}

__global__ void scan_partials_kernel(int* __restrict__ partials, int nb) {
    __shared__ int sm[128];
    const int tid = threadIdx.x;
    int v = (tid < nb) ? partials[tid] : 0;
    sm[tid] = v;
    __syncthreads();
#pragma unroll
    for (int o = 1; o < 128; o <<= 1) {
        int t = (tid >= o) ? sm[tid - o] : 0;
        __syncthreads();
        sm[tid] += t;
        __syncthreads();
    }
    if (tid < nb) partials[tid] = sm[tid] - v;
}

__global__ void scan_add_kernel(int* __restrict__ rowptr,
                                const int* __restrict__ partials,
                                int* __restrict__ fill, int n, int ne) {
    int i = blockIdx.x * blockDim.x + threadIdx.x;
    if (i < n) {
        int v = rowptr[i] + partials[i >> 10];
        rowptr[i] = v;
        fill[i] = v;
    }
    if (i == 0) rowptr[n] = ne;
}

__global__ void csr_fill_kernel(const void* __restrict__ ei,
                                const float* __restrict__ ew, int ne,
                                int* __restrict__ fill,
                                int2* __restrict__ epack) {
    int e = (blockIdx.x * blockDim.x + threadIdx.x) * 2;
    if (e >= ne) return;
    int s0, d0, s1 = -1, d1 = -1;
    float w0, w1 = 0.f;
    if (g_idx64) {
        const long long* ps = (const long long*)ei;
        const long long* pd = ps + ne;
        if (e + 1 < ne) {
            longlong2 sv = *(const longlong2*)(ps + e);
            longlong2 dv = *(const longlong2*)(pd + e);
            float2 wv = *(const float2*)(ew + e);
            s0 = (int)sv.x; s1 = (int)sv.y;
            d0 = (int)dv.x; d1 = (int)dv.y;
            w0 = wv.x; w1 = wv.y;
        } else { s0 = (int)ps[e]; d0 = (int)pd[e]; w0 = ew[e]; }
    } else {
        const int* ps = (const int*)ei;
        const int* pd = ps + ne;
        if (e + 1 < ne) {
            int2 sv = *(const int2*)(ps + e);
            int2 dv = *(const int2*)(pd + e);
            float2 wv = *(const float2*)(ew + e);
            s0 = sv.x; s1 = sv.y; d0 = dv.x; d1 = dv.y;
            w0 = wv.x; w1 = wv.y;
        } else { s0 = ps[e]; d0 = pd[e]; w0 = ew[e]; }
    }
    int p0 = atomicAdd(&fill[d0], 1);
    epack[p0] = make_int2(s0, __float_as_int(w0));
    if (s1 >= 0) {
        int p1 = atomicAdd(&fill[d1], 1);
        epack[p1] = make_int2(s1, __float_as_int(w1));
    }
}

// ------------- W prep: fp32 -> bf16 hi/lo for W1 and W2, fused -------------
__global__ void prep_w2_kernel(const float* __restrict__ Wa,
                               __nv_bfloat16* __restrict__ ahi,
                               __nv_bfloat16* __restrict__ alo,
                               const float* __restrict__ Wb,
                               __nv_bfloat16* __restrict__ bhi,
                               __nv_bfloat16* __restrict__ blo) {
    int i = blockIdx.x * blockDim.x + threadIdx.x;
    if (i < 128 * 128) {
        float w = Wa[i];
        __nv_bfloat16 h = __float2bfloat16_rn(w);
        ahi[i] = h;
        alo[i] = __float2bfloat16_rn(w - __bfloat162float(h));
    } else if (i < 2 * 128 * 128) {
        int k = i - 128 * 128;
        float w = Wb[k];
        __nv_bfloat16 h = __float2bfloat16_rn(w);
        bhi[k] = h;
        blo[k] = __float2bfloat16_rn(w - __bfloat162float(h));
    }
}

// -------------------- tensor-path GEMM (wmma bf16x3) -----------------------
__global__ void gemm128_tc_kernel(const float* __restrict__ X,
                                  const __nv_bfloat16* __restrict__ Whi,
                                  const __nv_bfloat16* __restrict__ Wlo,
                                  __half* __restrict__ Yh, int nrows) {
    extern __shared__ char smem[];
    __nv_bfloat16* xhi = (__nv_bfloat16*)smem;
    __nv_bfloat16* xlo = xhi + 64 * LDX;
    __nv_bfloat16* wh  = xlo + 64 * LDX;
    __nv_bfloat16* wl  = wh + 128 * LDW;
    const int tid = threadIdx.x;
    const int row0 = blockIdx.x * 64;

    {
        const float4* X4 = (const float4*)X;
#pragma unroll
        for (int i = tid; i < 64 * 32; i += 256) {
            int r = i >> 5, kq = i & 31;
            float4 v = (row0 + r < nrows)
                           ? X4[(size_t)(row0 + r) * 32 + kq]
                           : make_float4(0.f, 0.f, 0.f, 0.f);
            __nv_bfloat16 hx = __float2bfloat16_rn(v.x);
            __nv_bfloat16 hy = __float2bfloat16_rn(v.y);
            __nv_bfloat16 hz = __float2bfloat16_rn(v.z);
            __nv_bfloat16 hw = __float2bfloat16_rn(v.w);
            __nv_bfloat162 hp0 = __halves2bfloat162(hx, hy);
            __nv_bfloat162 hp1 = __halves2bfloat162(hz, hw);
            uint64_t hword = (uint64_t)(*(uint32_t*)&hp0)
                           | ((uint64_t)(*(uint32_t*)&hp1) << 32);
            *(uint64_t*)&xhi[r * LDX + kq * 4] = hword;
            __nv_bfloat162 lp0 = __halves2bfloat162(
                __float2bfloat16_rn(v.x - __bfloat162float(hx)),
                __float2bfloat16_rn(v.y - __bfloat162float(hy)));
            __nv_bfloat162 lp1 = __halves2bfloat162(
                __float2bfloat16_rn(v.z - __bfloat162float(hz)),
                __float2bfloat16_rn(v.w - __bfloat162float(hw)));
            uint64_t lword = (uint64_t)(*(uint32_t*)&lp0)
                           | ((uint64_t)(*(uint32_t*)&lp1) << 32);
            *(uint64_t*)&xlo[r * LDX + kq * 4] = lword;
        }
    }
    {
        const int4* h4 = (const int4*)Whi;
        const int4* l4 = (const int4*)Wlo;
#pragma unroll
        for (int i = tid; i < 2048; i += 256) {
            int k = i >> 4, seg = i & 15;
            *(int4*)&wh[k * LDW + seg * 8] = h4[i];
            *(int4*)&wl[k * LDW + seg * 8] = l4[i];
        }
    }
    __syncthreads();

    const int w  = tid >> 5;
    const int wr = w >> 2;
    const int wc = w & 3;

    wmma::fragment<wmma::accumulator, 16, 16, 16, float> acc[2][2];
#pragma unroll
    for (int i = 0; i < 2; i++)
#pragma unroll
        for (int j = 0; j < 2; j++) wmma::fill_fragment(acc[i][j], 0.f);

#pragma unroll
    for (int ks = 0; ks < 8; ks++) {
        const int k0 = ks * 16;
        wmma::fragment<wmma::matrix_a, 16, 16, 16, __nv_bfloat16,
                       wmma::row_major> ah[2], al[2];
        wmma::fragment<wmma::matrix_b, 16, 16, 16, __nv_bfloat16,
                       wmma::row_major> bh[2], bl[2];
#pragma unroll
        for (int i = 0; i < 2; i++) {
            wmma::load_matrix_sync(ah[i], &xhi[(wr * 32 + i * 16) * LDX + k0], LDX);
            wmma::load_matrix_sync(al[i], &xlo[(wr * 32 + i * 16) * LDX + k0], LDX);
        }
#pragma unroll
        for (int j = 0; j < 2; j++) {
            wmma::load_matrix_sync(bh[j], &wh[k0 * LDW + wc * 32 + j * 16], LDW);
            wmma::load_matrix_sync(bl[j], &wl[k0 * LDW + wc * 32 + j * 16], LDW);
        }
#pragma unroll
        for (int i = 0; i < 2; i++)
#pragma unroll
            for (int j = 0; j < 2; j++) {
                wmma::mma_sync(acc[i][j], ah[i], bh[j], acc[i][j]);
                wmma::mma_sync(acc[i][j], ah[i], bl[j], acc[i][j]);
                wmma::mma_sync(acc[i][j], al[i], bh[j], acc[i][j]);
            }
    }

    __syncthreads();
    float* stage = (float*)smem;
#pragma unroll
    for (int i = 0; i < 2; i++)
#pragma unroll
        for (int j = 0; j < 2; j++) {
            wmma::store_matrix_sync(&stage[(wr * 32 + i * 16) * LDS
                                           + wc * 32 + j * 16],
                                    acc[i][j], LDS, wmma::mem_row_major);
        }
    __syncthreads();
    __half2* Y2 = (__half2*)Yh;
#pragma unroll
    for (int i = tid; i < 64 * 64; i += 256) {
        int r = i >> 6, c2 = i & 63;
        float a = stage[r * LDS + 2 * c2];
        float b = stage[r * LDS + 2 * c2 + 1];
        Y2[(size_t)(row0 + r) * 64 + c2] = __floats2half2_rn(a, b);
    }
}

// ------------------------- SIMT GEMM, D_OUT=40 (fp16 out) ------------------
__global__ void gemm40_kernel(const float* __restrict__ X,
                              const float* __restrict__ W,
                              __half* __restrict__ Yh, int nrows) {
    extern __shared__ float sm[];
    float* Ws = sm;
    float* Xs = sm + 128 * DO;
    const int tid = threadIdx.x;

    for (int i = tid; i < 128 * DO; i += 320) Ws[i] = W[i];

    const int row0 = blockIdx.x * 64;
    const float4* X4 = (const float4*)X;
    float4* Xs4 = (float4*)Xs;
    for (int i = tid; i < 64 * 32; i += 320) {
        int gr = row0 + (i >> 5);
        Xs4[i] = (gr < nrows) ? X4[(size_t)gr * 32 + (i & 31)]
                              : make_float4(0.f, 0.f, 0.f, 0.f);
    }
    __syncthreads();

    const int c  = tid % DO;
    const int rg = tid / DO;
    float acc[8];
#pragma unroll
    for (int r = 0; r < 8; r++) acc[r] = 0.f;
    const float4* xb4 = (const float4*)(Xs + rg * 8 * 128);

#pragma unroll 4
    for (int k4 = 0; k4 < 32; k4++) {
        float w0 = Ws[(4 * k4 + 0) * DO + c];
        float w1 = Ws[(4 * k4 + 1) * DO + c];
        float w2 = Ws[(4 * k4 + 2) * DO + c];
        float w3 = Ws[(4 * k4 + 3) * DO + c];
#pragma unroll
        for (int r = 0; r < 8; r++) {
            float4 xv = xb4[r * 32 + k4];
            acc[r] += xv.x * w0 + xv.y * w1 + xv.z * w2 + xv.w * w3;
        }
    }
#pragma unroll
    for (int r = 0; r < 8; r++) {
        int gr = row0 + rg * 8 + r;
        if (gr < nrows) Yh[(size_t)gr * DO + c] = __float2half_rn(acc[r]);
    }
}

// ----------------------- CSR gather aggregation ----------------------------
// H in fp16 (256 B/row). Lane owns cols 4l..4l+3 = one uint2. Unroll 8.
__global__ void agg128_kernel(const int* __restrict__ rowptr,
                              const int2* __restrict__ epack,
                              const __half* __restrict__ H,
                              const float* __restrict__ bias,
                              float* __restrict__ Y, int n) {
    int node = blockIdx.x * 8 + (threadIdx.x >> 5);
    if (node >= n) return;
    const int lane = threadIdx.x & 31;
    int beg = rowptr[node];
    int end = rowptr[node + 1];

    float4 acc = make_float4(0.f, 0.f, 0.f, 0.f);
    int j = beg;
    for (; j + 7 < end; j += 8) {
        int2 ed[8];
        uint2 u[8];
#pragma unroll
        for (int q = 0; q < 8; q++) ed[q] = epack[j + q];
#pragma unroll
        for (int q = 0; q < 8; q++)
            u[q] = ((const uint2*)(H + (size_t)ed[q].x * 128))[lane];
#pragma unroll
        for (int q = 0; q < 8; q++) {
            float w = __int_as_float(ed[q].y);
            float2 a = __half22float2(*(__half2*)&u[q].x);
            float2 b = __half22float2(*(__half2*)&u[q].y);
            acc.x += a.x * w; acc.y += a.y * w;
            acc.z += b.x * w; acc.w += b.y * w;
        }
    }
    for (; j < end; j++) {
        int2 e = epack[j];
        float w = __int_as_float(e.y);
        uint2 u = ((const uint2*)(H + (size_t)e.x * 128))[lane];
        float2 a = __half22float2(*(__half2*)&u.x);
        float2 b = __half22float2(*(__half2*)&u.y);
        acc.x += a.x * w; acc.y += a.y * w;
        acc.z += b.x * w; acc.w += b.y * w;
    }

    float4 b = ((const float4*)bias)[lane];
    acc.x = fmaxf(acc.x + b.x, 0.f);
    acc.y = fmaxf(acc.y + b.y, 0.f);
    acc.z = fmaxf(acc.z + b.z, 0.f);
    acc.w = fmaxf(acc.w + b.w, 0.f);
    ((float4*)(Y + (size_t)node * 128))[lane] = acc;
}

// D=40 gather (fp16 H) + bias + log_softmax, one warp per node.
__global__ void agg40_lsm_kernel(const int* __restrict__ rowptr,
                                 const int2* __restrict__ epack,
                                 const __half* __restrict__ H,
                                 const float* __restrict__ b,
                                 float* __restrict__ out, int n) {
    int node = blockIdx.x * 8 + (threadIdx.x >> 5);
    if (node >= n) return;
    const int lane = threadIdx.x & 31;
    int beg = rowptr[node];
    int end = rowptr[node + 1];

    float a0 = 0.f, a1 = 0.f;
    int j = beg;
    for (; j + 1 < end; j += 2) {
        int2 e0 = epack[j]; int2 e1 = epack[j + 1];
        float w0 = __int_as_float(e0.y), w1 = __int_as_float(e1.y);
        const __half* h0 = H + (size_t)e0.x * DO;
        const __half* h1 = H + (size_t)e1.x * DO;
        a0 += __half2float(h0[lane]) * w0 + __half2float(h1[lane]) * w1;
        if (lane < 8)
            a1 += __half2float(h0[32 + lane]) * w0
                + __half2float(h1[32 + lane]) * w1;
    }
    if (j < end) {
        int2 e = epack[j];
        float w = __int_as_float(e.y);
        const __half* hs = H + (size_t)e.x * DO;
        a0 += __half2float(hs[lane]) * w;
        if (lane < 8) a1 += __half2float(hs[32 + lane]) * w;
    }

    float v0 = a0 + b[lane];
    float v1 = (lane < 8) ? (a1 + b[32 + lane]) : -1e30f;

    float m = fmaxf(v0, v1);
#pragma unroll
    for (int o = 16; o; o >>= 1) m = fmaxf(m, __shfl_xor_sync(0xffffffffu, m, o));

    float sum = __expf(v0 - m) + ((lane < 8) ? __expf(v1 - m) : 0.f);
#pragma unroll
    for (int o = 16; o; o >>= 1) sum += __shfl_xor_sync(0xffffffffu, sum, o);

    float lse = m + __logf(sum);
    out[(size_t)node * DO + lane] = v0 - lse;
    if (lane < 8) out[(size_t)node * DO + 32 + lane] = v1 - lse;
}

// ---------------------------------------------------------------------------
extern "C" void kernel_launch(void* const* d_in, const int* in_sizes, int n_in,
                              void* d_out, int out_size) {
    const float* x  = (const float*)d_in[0];
    const void*  ei = d_in[1];
    const float* ew = (const float*)d_in[2];
    const float* W1 = (const float*)d_in[3];
    const float* b1 = (const float*)d_in[4];
    const float* W2 = (const float*)d_in[5];
    const float* b2 = (const float*)d_in[6];
    const float* W3 = (const float*)d_in[7];
    const float* b3 = (const float*)d_in[8];
    float* out = (float*)d_out;

    const int n  = in_sizes[0] / DH;
    int ne = in_sizes[1] / 2;
    if (ne > MAXE) ne = MAXE;
    (void)n_in; (void)out_size;

    float *A, *B;
    int *rowptr, *deg, *fill, *partials;
    int2* epack;
    __nv_bfloat16 *w1hi, *w1lo, *w2hi, *w2lo;
    cudaGetSymbolAddress((void**)&A, g_bufA);
    cudaGetSymbolAddress((void**)&B, g_bufB);
    cudaGetSymbolAddress((void**)&rowptr, g_rowptr);
    cudaGetSymbolAddress((void**)&deg, g_deg);
    cudaGetSymbolAddress((void**)&fill, g_fill);
    cudaGetSymbolAddress((void**)&epack, g_epack);
    cudaGetSymbolAddress((void**)&partials, g_partials);
    cudaGetSymbolAddress((void**)&w1hi, g_w1hi);
    cudaGetSymbolAddress((void**)&w1lo, g_w1lo);
    cudaGetSymbolAddress((void**)&w2hi, g_w2hi);
    cudaGetSymbolAddress((void**)&w2lo, g_w2lo);

    __half* Ah = (__half*)A;

    const int SMEM_TC = (2 * 64 * LDX + 2 * 128 * LDW) * (int)sizeof(__nv_bfloat16);
    const int SMEM40  = (128 * DO + 64 * 128) * (int)sizeof(float);
    cudaFuncSetAttribute(gemm128_tc_kernel,
                         cudaFuncAttributeMaxDynamicSharedMemorySize, SMEM_TC);
    cudaFuncSetAttribute(gemm40_kernel,
                         cudaFuncAttributeMaxDynamicSharedMemorySize, SMEM40);

    const int tcBlocks       = (n + 63) / 64;
    const int nodeWarpBlocks = (n + 7) / 8;
    const int scanBlocks     = (n + 1023) / 1024;
    const int edge2Blocks    = ((ne + 1) / 2 + 255) / 256;

    static cudaStream_t s2 = nullptr;
    static cudaEvent_t evFork = nullptr, evJoin = nullptr;
    if (s2 == nullptr) {
        cudaStreamCreateWithFlags(&s2, cudaStreamNonBlocking);
        cudaEventCreateWithFlags(&evFork, cudaEventDisableTiming);
        cudaEventCreateWithFlags(&evJoin, cudaEventDisableTiming);
    }

    // ---- fork: CSR build on side stream ----
    cudaEventRecord(evFork, 0);
    cudaStreamWaitEvent(s2, evFork, 0);
    deg_zero_kernel<<<(n + 255) / 256, 256, 0, s2>>>(deg, n, ei, n);
    deg_count_kernel<<<edge2Blocks, 256, 0, s2>>>(ei, ne, deg);
    scan_block_kernel<<<scanBlocks, 1024, 0, s2>>>(deg, rowptr, partials, n);
    scan_partials_kernel<<<1, 128, 0, s2>>>(partials, scanBlocks);
    scan_add_kernel<<<(n + 255) / 256, 256, 0, s2>>>(rowptr, partials, fill, n, ne);
    csr_fill_kernel<<<edge2Blocks, 256, 0, s2>>>(ei, ew, ne, fill, epack);
    cudaEventRecord(evJoin, s2);

    // ---- main stream: W prep + layer-1 GEMM overlap the CSR build ----
    prep_w2_kernel<<<128, 256>>>(W1, w1hi, w1lo, W2, w2hi, w2lo);
    gemm128_tc_kernel<<<tcBlocks, 256, SMEM_TC>>>(x, w1hi, w1lo, Ah, n);

    // ---- join ----
    cudaStreamWaitEvent(0, evJoin, 0);

    // ---- layer 1 ----
    agg128_kernel<<<nodeWarpBlocks, 256>>>(rowptr, epack, Ah, b1, B, n);
    // ---- layer 2 ----
    gemm128_tc_kernel<<<tcBlocks, 256, SMEM_TC>>>(B, w2hi, w2lo, Ah, n);
    agg128_kernel<<<nodeWarpBlocks, 256>>>(rowptr, epack, Ah, b2, B, n);
    // ---- layer 3 (D_OUT = 40) ----
    gemm40_kernel<<<tcBlocks, 320, SMEM40>>>(B, W3, Ah, n);
    agg40_lsm_kernel<<<nodeWarpBlocks, 256>>>(rowptr, epack, Ah, b3, out, n);
}

// round 14
// speedup vs baseline: 1.2400x; 1.0694x over previous
#include <cuda_runtime.h>
#include <cuda_bf16.h>
#include <cuda_fp16.h>
#include <mma.h>
#include <cstdint>

using namespace nvcuda;

// ---------------------------------------------------------------------------
// AdjGCN: 3-layer GCN forward.  (R13 champion + fp16 inter-layer everywhere.)
//  - CSR-gather aggregation; CSR built on a forked stream; int2 edge payload.
//  - 128x128 GEMMs on wmma (HMMA), bf16x3 split, fp32 accumulate.
//  - ALL inter-layer tensors fp16; all accumulation fp32.
// ---------------------------------------------------------------------------

#define MAXN 100000
#define MAXNP 100096
#define MAXE 1600000
#define DH   128
#define DO   40
#define LDX  136
#define LDW  136
#define LDS  132

__device__ float         g_bufA[(size_t)MAXNP * DH];   // fp16 H (gemm outs)
__device__ float         g_bufB[(size_t)MAXNP * DH];   // fp16 agg outs
__device__ int           g_idx64;
__device__ int           g_rowptr[MAXN + 1];
__device__ int           g_deg[MAXN];
__device__ int           g_fill[MAXN];
__device__ int2          g_epack[MAXE];
__device__ int           g_partials[128];
__device__ __nv_bfloat16 g_w1hi[128 * 128];
__device__ __nv_bfloat16 g_w1lo[128 * 128];
__device__ __nv_bfloat16 g_w2hi[128 * 128];
__device__ __nv_bfloat16 g_w2lo[128 * 128];

// ------------------------------ CSR build ---------------------------------
__global__ void deg_zero_kernel(int* __restrict__ deg, int n,
                                const void* ei, int n_nodes) {
    int i = blockIdx.x * blockDim.x + threadIdx.x;
    if (i < n) deg[i] = 0;
    if (blockIdx.x == 0 && threadIdx.x == 0) {
        const long long* p = (const long long*)ei;
        int ok64 = 1;
        for (int k = 0; k < 32; k++) {
            long long v = p[k];
            if (v < 0 || v >= n_nodes) { ok64 = 0; break; }
        }
        g_idx64 = ok64;
    }
}

__global__ void deg_count_kernel(const void* __restrict__ ei, int ne,
                                 int* __restrict__ deg) {
    int e = (blockIdx.x * blockDim.x + threadIdx.x) * 2;
    if (e >= ne) return;
    int d0, d1 = -1;
    if (g_idx64) {
        const long long* p = (const long long*)ei + ne;
        if (e + 1 < ne) {
            longlong2 v = *(const longlong2*)(p + e);
            d0 = (int)v.x; d1 = (int)v.y;
        } else d0 = (int)p[e];
    } else {
        const int* p = (const int*)ei + ne;
        if (e + 1 < ne) {
            int2 v = *(const int2*)(p + e);
            d0 = v.x; d1 = v.y;
        } else d0 = p[e];
    }
    atomicAdd(&deg[d0], 1);
    if (d1 >= 0) atomicAdd(&deg[d1], 1);
}

__global__ void scan_block_kernel(const int* __restrict__ deg,
                                  int* __restrict__ rowptr,
                                  int* __restrict__ partials, int n) {
    __shared__ int sm[1024];
    const int tid = threadIdx.x;
    int i = blockIdx.x * 1024 + tid;
    int v = (i < n) ? deg[i] : 0;
    sm[tid] = v;
    __syncthreads();
#pragma unroll
    for (int o = 1; o < 1024; o <<= 1) {
        int t = (tid >= o) ? sm[tid - o] : 0;
        __syncthreads();
        sm[tid] += t;
        __syncthreads();
    }
    if (i < n) rowptr[i] = sm[tid] - v;
    if (tid == 1023) partials[blockIdx.x] = sm[1023];
}

__global__ void scan_partials_kernel(int* __restrict__ partials, int nb) {
    __shared__ int sm[128];
    const int tid = threadIdx.x;
    int v = (tid < nb) ? partials[tid] : 0;
    sm[tid] = v;
    __syncthreads();
#pragma unroll
    for (int o = 1; o < 128; o <<= 1) {
        int t = (tid >= o) ? sm[tid - o] : 0;
        __syncthreads();
        sm[tid] += t;
        __syncthreads();
    }
    if (tid < nb) partials[tid] = sm[tid] - v;
}

__global__ void scan_add_kernel(int* __restrict__ rowptr,
                                const int* __restrict__ partials,
                                int* __restrict__ fill, int n, int ne) {
    int i = blockIdx.x * blockDim.x + threadIdx.x;
    if (i < n) {
        int v = rowptr[i] + partials[i >> 10];
        rowptr[i] = v;
        fill[i] = v;
    }
    if (i == 0) rowptr[n] = ne;
}

__global__ void csr_fill_kernel(const void* __restrict__ ei,
                                const float* __restrict__ ew, int ne,
                                int* __restrict__ fill,
                                int2* __restrict__ epack) {
    int e = (blockIdx.x * blockDim.x + threadIdx.x) * 2;
    if (e >= ne) return;
    int s0, d0, s1 = -1, d1 = -1;
    float w0, w1 = 0.f;
    if (g_idx64) {
        const long long* ps = (const long long*)ei;
        const long long* pd = ps + ne;
        if (e + 1 < ne) {
            longlong2 sv = *(const longlong2*)(ps + e);
            longlong2 dv = *(const longlong2*)(pd + e);
            float2 wv = *(const float2*)(ew + e);
            s0 = (int)sv.x; s1 = (int)sv.y;
            d0 = (int)dv.x; d1 = (int)dv.y;
            w0 = wv.x; w1 = wv.y;
        } else { s0 = (int)ps[e]; d0 = (int)pd[e]; w0 = ew[e]; }
    } else {
        const int* ps = (const int*)ei;
        const int* pd = ps + ne;
        if (e + 1 < ne) {
            int2 sv = *(const int2*)(ps + e);
            int2 dv = *(const int2*)(pd + e);
            float2 wv = *(const float2*)(ew + e);
            s0 = sv.x; s1 = sv.y; d0 = dv.x; d1 = dv.y;
            w0 = wv.x; w1 = wv.y;
        } else { s0 = ps[e]; d0 = pd[e]; w0 = ew[e]; }
    }
    int p0 = atomicAdd(&fill[d0], 1);
    epack[p0] = make_int2(s0, __float_as_int(w0));
    if (s1 >= 0) {
        int p1 = atomicAdd(&fill[d1], 1);
        epack[p1] = make_int2(s1, __float_as_int(w1));
    }
}

// ------------- W prep: fp32 -> bf16 hi/lo for W1 and W2, fused -------------
__global__ void prep_w2_kernel(const float* __restrict__ Wa,
                               __nv_bfloat16* __restrict__ ahi,
                               __nv_bfloat16* __restrict__ alo,
                               const float* __restrict__ Wb,
                               __nv_bfloat16* __restrict__ bhi,
                               __nv_bfloat16* __restrict__ blo) {
    int i = blockIdx.x * blockDim.x + threadIdx.x;
    if (i < 128 * 128) {
        float w = Wa[i];
        __nv_bfloat16 h = __float2bfloat16_rn(w);
        ahi[i] = h;
        alo[i] = __float2bfloat16_rn(w - __bfloat162float(h));
    } else if (i < 2 * 128 * 128) {
        int k = i - 128 * 128;
        float w = Wb[k];
        __nv_bfloat16 h = __float2bfloat16_rn(w);
        bhi[k] = h;
        blo[k] = __float2bfloat16_rn(w - __bfloat162float(h));
    }
}

// ------------------ bf16 hi/lo packing helpers -----------------------------
__device__ __forceinline__ uint64_t pack4_hi(float a, float b, float c, float d) {
    __nv_bfloat162 p0 = __floats2bfloat162_rn(a, b);
    __nv_bfloat162 p1 = __floats2bfloat162_rn(c, d);
    return (uint64_t)(*(uint32_t*)&p0) | ((uint64_t)(*(uint32_t*)&p1) << 32);
}
__device__ __forceinline__ uint64_t pack4_lo(float a, float b, float c, float d) {
    float ah = __bfloat162float(__float2bfloat16_rn(a));
    float bh = __bfloat162float(__float2bfloat16_rn(b));
    float ch = __bfloat162float(__float2bfloat16_rn(c));
    float dh = __bfloat162float(__float2bfloat16_rn(d));
    __nv_bfloat162 p0 = __floats2bfloat162_rn(a - ah, b - bh);
    __nv_bfloat162 p1 = __floats2bfloat162_rn(c - ch, d - dh);
    return (uint64_t)(*(uint32_t*)&p0) | ((uint64_t)(*(uint32_t*)&p1) << 32);
}

// --------------- wmma bf16x3 mainloop + fp16 epilogue ----------------------
__device__ __forceinline__ void wmma_mainloop_epilogue(
    char* smem, __nv_bfloat16* xhi, __nv_bfloat16* xlo,
    __nv_bfloat16* wh, __nv_bfloat16* wl,
    __half* __restrict__ Yh, int row0, int tid) {
    const int w  = tid >> 5;
    const int wr = w >> 2;
    const int wc = w & 3;

    wmma::fragment<wmma::accumulator, 16, 16, 16, float> acc[2][2];
#pragma unroll
    for (int i = 0; i < 2; i++)
#pragma unroll
        for (int j = 0; j < 2; j++) wmma::fill_fragment(acc[i][j], 0.f);

#pragma unroll
    for (int ks = 0; ks < 8; ks++) {
        const int k0 = ks * 16;
        wmma::fragment<wmma::matrix_a, 16, 16, 16, __nv_bfloat16,
                       wmma::row_major> ah[2], al[2];
        wmma::fragment<wmma::matrix_b, 16, 16, 16, __nv_bfloat16,
                       wmma::row_major> bh[2], bl[2];
#pragma unroll
        for (int i = 0; i < 2; i++) {
            wmma::load_matrix_sync(ah[i], &xhi[(wr * 32 + i * 16) * LDX + k0], LDX);
            wmma::load_matrix_sync(al[i], &xlo[(wr * 32 + i * 16) * LDX + k0], LDX);
        }
#pragma unroll
        for (int j = 0; j < 2; j++) {
            wmma::load_matrix_sync(bh[j], &wh[k0 * LDW + wc * 32 + j * 16], LDW);
            wmma::load_matrix_sync(bl[j], &wl[k0 * LDW + wc * 32 + j * 16], LDW);
        }
#pragma unroll
        for (int i = 0; i < 2; i++)
#pragma unroll
            for (int j = 0; j < 2; j++) {
                wmma::mma_sync(acc[i][j], ah[i], bh[j], acc[i][j]);
                wmma::mma_sync(acc[i][j], ah[i], bl[j], acc[i][j]);
                wmma::mma_sync(acc[i][j], al[i], bh[j], acc[i][j]);
            }
    }

    __syncthreads();
    float* stage = (float*)smem;
#pragma unroll
    for (int i = 0; i < 2; i++)
#pragma unroll
        for (int j = 0; j < 2; j++) {
            wmma::store_matrix_sync(&stage[(wr * 32 + i * 16) * LDS
                                           + wc * 32 + j * 16],
                                    acc[i][j], LDS, wmma::mem_row_major);
        }
    __syncthreads();
    __half2* Y2 = (__half2*)Yh;
#pragma unroll
    for (int i = tid; i < 64 * 64; i += 256) {
        int r = i >> 6, c2 = i & 63;
        float a = stage[r * LDS + 2 * c2];
        float b = stage[r * LDS + 2 * c2 + 1];
        Y2[(size_t)(row0 + r) * 64 + c2] = __floats2half2_rn(a, b);
    }
}

// ---------- layer-1 GEMM: fp32 X in -> fp16 H out --------------------------
__global__ void gemm128_tc_kernel(const float* __restrict__ X,
                                  const __nv_bfloat16* __restrict__ Whi,
                                  const __nv_bfloat16* __restrict__ Wlo,
                                  __half* __restrict__ Yh, int nrows) {
    extern __shared__ char smem[];
    __nv_bfloat16* xhi = (__nv_bfloat16*)smem;
    __nv_bfloat16* xlo = xhi + 64 * LDX;
    __nv_bfloat16* wh  = xlo + 64 * LDX;
    __nv_bfloat16* wl  = wh + 128 * LDW;
    const int tid = threadIdx.x;
    const int row0 = blockIdx.x * 64;

    {
        const float4* X4 = (const float4*)X;
#pragma unroll
        for (int i = tid; i < 64 * 32; i += 256) {
            int r = i >> 5, kq = i & 31;
            float4 v = (row0 + r < nrows)
                           ? X4[(size_t)(row0 + r) * 32 + kq]
                           : make_float4(0.f, 0.f, 0.f, 0.f);
            *(uint64_t*)&xhi[r * LDX + kq * 4] = pack4_hi(v.x, v.y, v.z, v.w);
            *(uint64_t*)&xlo[r * LDX + kq * 4] = pack4_lo(v.x, v.y, v.z, v.w);
        }
    }
    {
        const int4* h4 = (const int4*)Whi;
        const int4* l4 = (const int4*)Wlo;
#pragma unroll
        for (int i = tid; i < 2048; i += 256) {
            int k = i >> 4, seg = i & 15;
            *(int4*)&wh[k * LDW + seg * 8] = h4[i];
            *(int4*)&wl[k * LDW + seg * 8] = l4[i];
        }
    }
    __syncthreads();
    wmma_mainloop_epilogue(smem, xhi, xlo, wh, wl, Yh, row0, tid);
}

// ---------- layer-2 GEMM: fp16 X in -> fp16 H out --------------------------
__global__ void gemm128_tc_h_kernel(const __half* __restrict__ X16,
                                    const __nv_bfloat16* __restrict__ Whi,
                                    const __nv_bfloat16* __restrict__ Wlo,
                                    __half* __restrict__ Yh, int nrows) {
    extern __shared__ char smem[];
    __nv_bfloat16* xhi = (__nv_bfloat16*)smem;
    __nv_bfloat16* xlo = xhi + 64 * LDX;
    __nv_bfloat16* wh  = xlo + 64 * LDX;
    __nv_bfloat16* wl  = wh + 128 * LDW;
    const int tid = threadIdx.x;
    const int row0 = blockIdx.x * 64;

    {
        const uint2* X2 = (const uint2*)X16;   // 4 halves per uint2
#pragma unroll
        for (int i = tid; i < 64 * 32; i += 256) {
            int r = i >> 5, kq = i & 31;
            float x0 = 0.f, x1 = 0.f, x2 = 0.f, x3 = 0.f;
            if (row0 + r < nrows) {
                uint2 u = X2[(size_t)(row0 + r) * 32 + kq];
                float2 a = __half22float2(*(__half2*)&u.x);
                float2 b = __half22float2(*(__half2*)&u.y);
                x0 = a.x; x1 = a.y; x2 = b.x; x3 = b.y;
            }
            *(uint64_t*)&xhi[r * LDX + kq * 4] = pack4_hi(x0, x1, x2, x3);
            *(uint64_t*)&xlo[r * LDX + kq * 4] = pack4_lo(x0, x1, x2, x3);
        }
    }
    {
        const int4* h4 = (const int4*)Whi;
        const int4* l4 = (const int4*)Wlo;
#pragma unroll
        for (int i = tid; i < 2048; i += 256) {
            int k = i >> 4, seg = i & 15;
            *(int4*)&wh[k * LDW + seg * 8] = h4[i];
            *(int4*)&wl[k * LDW + seg * 8] = l4[i];
        }
    }
    __syncthreads();
    wmma_mainloop_epilogue(smem, xhi, xlo, wh, wl, Yh, row0, tid);
}

// ---------------- SIMT GEMM, D_OUT=40 (fp16 in, fp16 out) ------------------
__global__ void gemm40_kernel(const __half* __restrict__ X16,
                              const float* __restrict__ W,
                              __half* __restrict__ Yh, int nrows) {
    extern __shared__ float sm[];
    float* Ws = sm;
    float* Xs = sm + 128 * DO;
    const int tid = threadIdx.x;

    for (int i = tid; i < 128 * DO; i += 320) Ws[i] = W[i];

    const int row0 = blockIdx.x * 64;
    const uint2* X2 = (const uint2*)X16;
    for (int i = tid; i < 64 * 32; i += 320) {
        int r = i >> 5, kq = i & 31;
        float4 v = make_float4(0.f, 0.f, 0.f, 0.f);
        if (row0 + r < nrows) {
            uint2 u = X2[(size_t)(row0 + r) * 32 + kq];
            float2 a = __half22float2(*(__half2*)&u.x);
            float2 b = __half22float2(*(__half2*)&u.y);
            v = make_float4(a.x, a.y, b.x, b.y);
        }
        *(float4*)&Xs[r * 128 + kq * 4] = v;
    }
    __syncthreads();

    const int c  = tid % DO;
    const int rg = tid / DO;
    float acc[8];
#pragma unroll
    for (int r = 0; r < 8; r++) acc[r] = 0.f;
    const float4* xb4 = (const float4*)(Xs + rg * 8 * 128);

#pragma unroll 4
    for (int k4 = 0; k4 < 32; k4++) {
        float w0 = Ws[(4 * k4 + 0) * DO + c];
        float w1 = Ws[(4 * k4 + 1) * DO + c];
        float w2 = Ws[(4 * k4 + 2) * DO + c];
        float w3 = Ws[(4 * k4 + 3) * DO + c];
#pragma unroll
        for (int r = 0; r < 8; r++) {
            float4 xv = xb4[r * 32 + k4];
            acc[r] += xv.x * w0 + xv.y * w1 + xv.z * w2 + xv.w * w3;
        }
    }
#pragma unroll
    for (int r = 0; r < 8; r++) {
        int gr = row0 + rg * 8 + r;
        if (gr < nrows) Yh[(size_t)gr * DO + c] = __float2half_rn(acc[r]);
    }
}

// ----------------------- CSR gather aggregation ----------------------------
// fp16 in, fp16 out. Unroll 8. Lane owns 4 cols (uint2 in/out).
__global__ void agg128_kernel(const int* __restrict__ rowptr,
                              const int2* __restrict__ epack,
                              const __half* __restrict__ H,
                              const float* __restrict__ bias,
                              __half* __restrict__ Y, int n) {
    int node = blockIdx.x * 8 + (threadIdx.x >> 5);
    if (node >= n) return;
    const int lane = threadIdx.x & 31;
    int beg = rowptr[node];
    int end = rowptr[node + 1];

    float4 acc = make_float4(0.f, 0.f, 0.f, 0.f);
    int j = beg;
    for (; j + 7 < end; j += 8) {
        int2 ed[8];
        uint2 u[8];
#pragma unroll
        for (int q = 0; q < 8; q++) ed[q] = epack[j + q];
#pragma unroll
        for (int q = 0; q < 8; q++)
            u[q] = ((const uint2*)(H + (size_t)ed[q].x * 128))[lane];
#pragma unroll
        for (int q = 0; q < 8; q++) {
            float w = __int_as_float(ed[q].y);
            float2 a = __half22float2(*(__half2*)&u[q].x);
            float2 b = __half22float2(*(__half2*)&u[q].y);
            acc.x += a.x * w; acc.y += a.y * w;
            acc.z += b.x * w; acc.w += b.y * w;
        }
    }
    for (; j < end; j++) {
        int2 e = epack[j];
        float w = __int_as_float(e.y);
        uint2 u = ((const uint2*)(H + (size_t)e.x * 128))[lane];
        float2 a = __half22float2(*(__half2*)&u.x);
        float2 b = __half22float2(*(__half2*)&u.y);
        acc.x += a.x * w; acc.y += a.y * w;
        acc.z += b.x * w; acc.w += b.y * w;
    }

    float4 b4 = ((const float4*)bias)[lane];
    acc.x = fmaxf(acc.x + b4.x, 0.f);
    acc.y = fmaxf(acc.y + b4.y, 0.f);
    acc.z = fmaxf(acc.z + b4.z, 0.f);
    acc.w = fmaxf(acc.w + b4.w, 0.f);
    __half2 h0 = __floats2half2_rn(acc.x, acc.y);
    __half2 h1 = __floats2half2_rn(acc.z, acc.w);
    uint2 o;
    o.x = *(uint32_t*)&h0;
    o.y = *(uint32_t*)&h1;
    ((uint2*)(Y + (size_t)node * 128))[lane] = o;
}

// D=40 gather (fp16 H) + bias + log_softmax, one warp per node, unroll 4.
__global__ void agg40_lsm_kernel(const int* __restrict__ rowptr,
                                 const int2* __restrict__ epack,
                                 const __half* __restrict__ H,
                                 const float* __restrict__ b,
                                 float* __restrict__ out, int n) {
    int node = blockIdx.x * 8 + (threadIdx.x >> 5);
    if (node >= n) return;
    const int lane = threadIdx.x & 31;
    int beg = rowptr[node];
    int end = rowptr[node + 1];

    float a0 = 0.f, a1 = 0.f;
    int j = beg;
    for (; j + 3 < end; j += 4) {
        int2 ed[4];
#pragma unroll
        for (int q = 0; q < 4; q++) ed[q] = epack[j + q];
        __half v0[4], v1[4];
#pragma unroll
        for (int q = 0; q < 4; q++) {
            const __half* hs = H + (size_t)ed[q].x * DO;
            v0[q] = hs[lane];
            v1[q] = (lane < 8) ? hs[32 + lane] : __half(0.f);
        }
#pragma unroll
        for (int q = 0; q < 4; q++) {
            float w = __int_as_float(ed[q].y);
            a0 += __half2float(v0[q]) * w;
            a1 += __half2float(v1[q]) * w;
        }
    }
    for (; j < end; j++) {
        int2 e = epack[j];
        float w = __int_as_float(e.y);
        const __half* hs = H + (size_t)e.x * DO;
        a0 += __half2float(hs[lane]) * w;
        if (lane < 8) a1 += __half2float(hs[32 + lane]) * w;
    }

    float v0 = a0 + b[lane];
    float v1 = (lane < 8) ? (a1 + b[32 + lane]) : -1e30f;

    float m = fmaxf(v0, v1);
#pragma unroll
    for (int o = 16; o; o >>= 1) m = fmaxf(m, __shfl_xor_sync(0xffffffffu, m, o));

    float sum = __expf(v0 - m) + ((lane < 8) ? __expf(v1 - m) : 0.f);
#pragma unroll
    for (int o = 16; o; o >>= 1) sum += __shfl_xor_sync(0xffffffffu, sum, o);

    float lse = m + __logf(sum);
    out[(size_t)node * DO + lane] = v0 - lse;
    if (lane < 8) out[(size_t)node * DO + 32 + lane] = v1 - lse;
}

// ---------------------------------------------------------------------------
extern "C" void kernel_launch(void* const* d_in, const int* in_sizes, int n_in,
                              void* d_out, int out_size) {
    const float* x  = (const float*)d_in[0];
    const void*  ei = d_in[1];
    const float* ew = (const float*)d_in[2];
    const float* W1 = (const float*)d_in[3];
    const float* b1 = (const float*)d_in[4];
    const float* W2 = (const float*)d_in[5];
    const float* b2 = (const float*)d_in[6];
    const float* W3 = (const float*)d_in[7];
    const float* b3 = (const float*)d_in[8];
    float* out = (float*)d_out;

    const int n  = in_sizes[0] / DH;
    int ne = in_sizes[1] / 2;
    if (ne > MAXE) ne = MAXE;
    (void)n_in; (void)out_size;

    float *A, *B;
    int *rowptr, *deg, *fill, *partials;
    int2* epack;
    __nv_bfloat16 *w1hi, *w1lo, *w2hi, *w2lo;
    cudaGetSymbolAddress((void**)&A, g_bufA);
    cudaGetSymbolAddress((void**)&B, g_bufB);
    cudaGetSymbolAddress((void**)&rowptr, g_rowptr);
    cudaGetSymbolAddress((void**)&deg, g_deg);
    cudaGetSymbolAddress((void**)&fill, g_fill);
    cudaGetSymbolAddress((void**)&epack, g_epack);
    cudaGetSymbolAddress((void**)&partials, g_partials);
    cudaGetSymbolAddress((void**)&w1hi, g_w1hi);
    cudaGetSymbolAddress((void**)&w1lo, g_w1lo);
    cudaGetSymbolAddress((void**)&w2hi, g_w2hi);
    cudaGetSymbolAddress((void**)&w2lo, g_w2lo);

    __half* Ah = (__half*)A;    // gemm outputs (H)
    __half* Bh = (__half*)B;    // agg outputs

    const int SMEM_TC = (2 * 64 * LDX + 2 * 128 * LDW) * (int)sizeof(__nv_bfloat16);
    const int SMEM40  = (128 * DO + 64 * 128) * (int)sizeof(float);
    cudaFuncSetAttribute(gemm128_tc_kernel,
                         cudaFuncAttributeMaxDynamicSharedMemorySize, SMEM_TC);
    cudaFuncSetAttribute(gemm128_tc_h_kernel,
                         cudaFuncAttributeMaxDynamicSharedMemorySize, SMEM_TC);
    cudaFuncSetAttribute(gemm40_kernel,
                         cudaFuncAttributeMaxDynamicSharedMemorySize, SMEM40);

    const int tcBlocks       = (n + 63) / 64;
    const int nodeWarpBlocks = (n + 7) / 8;
    const int scanBlocks     = (n + 1023) / 1024;
    const int edge2Blocks    = ((ne + 1) / 2 + 255) / 256;

    static cudaStream_t s2 = nullptr;
    static cudaEvent_t evFork = nullptr, evJoin = nullptr;
    if (s2 == nullptr) {
        cudaStreamCreateWithFlags(&s2, cudaStreamNonBlocking);
        cudaEventCreateWithFlags(&evFork, cudaEventDisableTiming);
        cudaEventCreateWithFlags(&evJoin, cudaEventDisableTiming);
    }

    // ---- fork: CSR build on side stream ----
    cudaEventRecord(evFork, 0);
    cudaStreamWaitEvent(s2, evFork, 0);
    deg_zero_kernel<<<(n + 255) / 256, 256, 0, s2>>>(deg, n, ei, n);
    deg_count_kernel<<<edge2Blocks, 256, 0, s2>>>(ei, ne, deg);
    scan_block_kernel<<<scanBlocks, 1024, 0, s2>>>(deg, rowptr, partials, n);
    scan_partials_kernel<<<1, 128, 0, s2>>>(partials, scanBlocks);
    scan_add_kernel<<<(n + 255) / 256, 256, 0, s2>>>(rowptr, partials, fill, n, ne);
    csr_fill_kernel<<<edge2Blocks, 256, 0, s2>>>(ei, ew, ne, fill, epack);
    cudaEventRecord(evJoin, s2);

    // ---- main stream: W prep + layer-1 GEMM overlap the CSR build ----
    prep_w2_kernel<<<128, 256>>>(W1, w1hi, w1lo, W2, w2hi, w2lo);
    gemm128_tc_kernel<<<tcBlocks, 256, SMEM_TC>>>(x, w1hi, w1lo, Ah, n);

    // ---- join ----
    cudaStreamWaitEvent(0, evJoin, 0);

    // ---- layer 1 ----
    agg128_kernel<<<nodeWarpBlocks, 256>>>(rowptr, epack, Ah, b1, Bh, n);
    // ---- layer 2 ----
    gemm128_tc_h_kernel<<<tcBlocks, 256, SMEM_TC>>>(Bh, w2hi, w2lo, Ah, n);
    agg128_kernel<<<nodeWarpBlocks, 256>>>(rowptr, epack, Ah, b2, Bh, n);
    // ---- layer 3 (D_OUT = 40) ----
    gemm40_kernel<<<tcBlocks, 320, SMEM40>>>(Bh, W3, Ah, n);
    agg40_lsm_kernel<<<nodeWarpBlocks, 256>>>(rowptr, epack, Ah, b3, out, n);
}

// round 15
// speedup vs baseline: 1.2838x; 1.0353x over previous
#include <cuda_runtime.h>
#include <cuda_bf16.h>
#include <cuda_fp16.h>
#include <mma.h>
#include <cstdint>

using namespace nvcuda;

// ---------------------------------------------------------------------------
// AdjGCN: 3-layer GCN forward.
//  - CSR-gather aggregation; CSR built on a forked stream; int2 edge payload.
//  - Layer-1 GEMM: bf16x3 wmma (fp32 X input). Layer-2 GEMM: fp16 X (exact)
//    x fp16 W hi/lo, 2 MMA passes, fp32 accumulate (residual ~2^-21).
//  - ALL inter-layer tensors fp16; all accumulation fp32.
// ---------------------------------------------------------------------------

#define MAXN 100000
#define MAXNP 100096
#define MAXE 1600000
#define DH   128
#define DO   40
#define LDX  136
#define LDW  136
#define LDS  132

__device__ float         g_bufA[(size_t)MAXNP * DH];   // fp16 H (gemm outs)
__device__ float         g_bufB[(size_t)MAXNP * DH];   // fp16 agg outs
__device__ int           g_idx64;
__device__ int           g_rowptr[MAXN + 1];
__device__ int           g_deg[MAXN];
__device__ int           g_fill[MAXN];
__device__ int2          g_epack[MAXE];
__device__ int           g_partials[128];
__device__ __nv_bfloat16 g_w1hi[128 * 128];
__device__ __nv_bfloat16 g_w1lo[128 * 128];
__device__ __half        g_w2hi[128 * 128];
__device__ __half        g_w2lo[128 * 128];

// ------------------------------ CSR build ---------------------------------
__global__ void deg_zero_kernel(int* __restrict__ deg, int n,
                                const void* ei, int n_nodes) {
    int i = blockIdx.x * blockDim.x + threadIdx.x;
    if (i < n) deg[i] = 0;
    if (blockIdx.x == 0 && threadIdx.x == 0) {
        const long long* p = (const long long*)ei;
        int ok64 = 1;
        for (int k = 0; k < 32; k++) {
            long long v = p[k];
            if (v < 0 || v >= n_nodes) { ok64 = 0; break; }
        }
        g_idx64 = ok64;
    }
}

__global__ void deg_count_kernel(const void* __restrict__ ei, int ne,
                                 int* __restrict__ deg) {
    int e = (blockIdx.x * blockDim.x + threadIdx.x) * 2;
    if (e >= ne) return;
    int d0, d1 = -1;
    if (g_idx64) {
        const long long* p = (const long long*)ei + ne;
        if (e + 1 < ne) {
            longlong2 v = *(const longlong2*)(p + e);
            d0 = (int)v.x; d1 = (int)v.y;
        } else d0 = (int)p[e];
    } else {
        const int* p = (const int*)ei + ne;
        if (e + 1 < ne) {
            int2 v = *(const int2*)(p + e);
            d0 = v.x; d1 = v.y;
        } else d0 = p[e];
    }
    atomicAdd(&deg[d0], 1);
    if (d1 >= 0) atomicAdd(&deg[d1], 1);
}

__global__ void scan_block_kernel(const int* __restrict__ deg,
                                  int* __restrict__ rowptr,
                                  int* __restrict__ partials, int n) {
    __shared__ int sm[1024];
    const int tid = threadIdx.x;
    int i = blockIdx.x * 1024 + tid;
    int v = (i < n) ? deg[i] : 0;
    sm[tid] = v;
    __syncthreads();
#pragma unroll
    for (int o = 1; o < 1024; o <<= 1) {
        int t = (tid >= o) ? sm[tid - o] : 0;
        __syncthreads();
        sm[tid] += t;
        __syncthreads();
    }
    if (i < n) rowptr[i] = sm[tid] - v;
    if (tid == 1023) partials[blockIdx.x] = sm[1023];
}

__global__ void scan_partials_kernel(int* __restrict__ partials, int nb) {
    __shared__ int sm[128];
    const int tid = threadIdx.x;
    int v = (tid < nb) ? partials[tid] : 0;
    sm[tid] = v;
    __syncthreads();
#pragma unroll
    for (int o = 1; o < 128; o <<= 1) {
        int t = (tid >= o) ? sm[tid - o] : 0;
        __syncthreads();
        sm[tid] += t;
        __syncthreads();
    }
    if (tid < nb) partials[tid] = sm[tid] - v;
}

__global__ void scan_add_kernel(int* __restrict__ rowptr,
                                const int* __restrict__ partials,
                                int* __restrict__ fill, int n, int ne) {
    int i = blockIdx.x * blockDim.x + threadIdx.x;
    if (i < n) {
        int v = rowptr[i] + partials[i >> 10];
        rowptr[i] = v;
        fill[i] = v;
    }
    if (i == 0) rowptr[n] = ne;
}

__global__ void csr_fill_kernel(const void* __restrict__ ei,
                                const float* __restrict__ ew, int ne,
                                int* __restrict__ fill,
                                int2* __restrict__ epack) {
    int e = (blockIdx.x * blockDim.x + threadIdx.x) * 2;
    if (e >= ne) return;
    int s0, d0, s1 = -1, d1 = -1;
    float w0, w1 = 0.f;
    if (g_idx64) {
        const long long* ps = (const long long*)ei;
        const long long* pd = ps + ne;
        if (e + 1 < ne) {
            longlong2 sv = *(const longlong2*)(ps + e);
            longlong2 dv = *(const longlong2*)(pd + e);
            float2 wv = *(const float2*)(ew + e);
            s0 = (int)sv.x; s1 = (int)sv.y;
            d0 = (int)dv.x; d1 = (int)dv.y;
            w0 = wv.x; w1 = wv.y;
        } else { s0 = (int)ps[e]; d0 = (int)pd[e]; w0 = ew[e]; }
    } else {
        const int* ps = (const int*)ei;
        const int* pd = ps + ne;
        if (e + 1 < ne) {
            int2 sv = *(const int2*)(ps + e);
            int2 dv = *(const int2*)(pd + e);
            float2 wv = *(const float2*)(ew + e);
            s0 = sv.x; s1 = sv.y; d0 = dv.x; d1 = dv.y;
            w0 = wv.x; w1 = wv.y;
        } else { s0 = ps[e]; d0 = pd[e]; w0 = ew[e]; }
    }
    int p0 = atomicAdd(&fill[d0], 1);
    epack[p0] = make_int2(s0, __float_as_int(w0));
    if (s1 >= 0) {
        int p1 = atomicAdd(&fill[d1], 1);
        epack[p1] = make_int2(s1, __float_as_int(w1));
    }
}

// ---- W prep: W1 -> bf16 hi/lo; W2 -> fp16 hi/lo ---------------------------
__global__ void prep_w2_kernel(const float* __restrict__ Wa,
                               __nv_bfloat16* __restrict__ ahi,
                               __nv_bfloat16* __restrict__ alo,
                               const float* __restrict__ Wb,
                               __half* __restrict__ bhi,
                               __half* __restrict__ blo) {
    int i = blockIdx.x * blockDim.x + threadIdx.x;
    if (i < 128 * 128) {
        float w = Wa[i];
        __nv_bfloat16 h = __float2bfloat16_rn(w);
        ahi[i] = h;
        alo[i] = __float2bfloat16_rn(w - __bfloat162float(h));
    } else if (i < 2 * 128 * 128) {
        int k = i - 128 * 128;
        float w = Wb[k];
        __half h = __float2half_rn(w);
        bhi[k] = h;
        blo[k] = __float2half_rn(w - __half2float(h));
    }
}

// ------------------ bf16 hi/lo packing helpers -----------------------------
__device__ __forceinline__ uint64_t pack4_hi(float a, float b, float c, float d) {
    __nv_bfloat162 p0 = __floats2bfloat162_rn(a, b);
    __nv_bfloat162 p1 = __floats2bfloat162_rn(c, d);
    return (uint64_t)(*(uint32_t*)&p0) | ((uint64_t)(*(uint32_t*)&p1) << 32);
}
__device__ __forceinline__ uint64_t pack4_lo(float a, float b, float c, float d) {
    float ah = __bfloat162float(__float2bfloat16_rn(a));
    float bh = __bfloat162float(__float2bfloat16_rn(b));
    float ch = __bfloat162float(__float2bfloat16_rn(c));
    float dh = __bfloat162float(__float2bfloat16_rn(d));
    __nv_bfloat162 p0 = __floats2bfloat162_rn(a - ah, b - bh);
    __nv_bfloat162 p1 = __floats2bfloat162_rn(c - ch, d - dh);
    return (uint64_t)(*(uint32_t*)&p0) | ((uint64_t)(*(uint32_t*)&p1) << 32);
}

// ---------- layer-1 GEMM: fp32 X -> bf16x3 wmma -> fp16 H ------------------
__global__ void gemm128_tc_kernel(const float* __restrict__ X,
                                  const __nv_bfloat16* __restrict__ Whi,
                                  const __nv_bfloat16* __restrict__ Wlo,
                                  __half* __restrict__ Yh, int nrows) {
    extern __shared__ char smem[];
    __nv_bfloat16* xhi = (__nv_bfloat16*)smem;
    __nv_bfloat16* xlo = xhi + 64 * LDX;
    __nv_bfloat16* wh  = xlo + 64 * LDX;
    __nv_bfloat16* wl  = wh + 128 * LDW;
    const int tid = threadIdx.x;
    const int row0 = blockIdx.x * 64;

    {
        const float4* X4 = (const float4*)X;
#pragma unroll
        for (int i = tid; i < 64 * 32; i += 256) {
            int r = i >> 5, kq = i & 31;
            float4 v = (row0 + r < nrows)
                           ? X4[(size_t)(row0 + r) * 32 + kq]
                           : make_float4(0.f, 0.f, 0.f, 0.f);
            *(uint64_t*)&xhi[r * LDX + kq * 4] = pack4_hi(v.x, v.y, v.z, v.w);
            *(uint64_t*)&xlo[r * LDX + kq * 4] = pack4_lo(v.x, v.y, v.z, v.w);
        }
    }
    {
        const int4* h4 = (const int4*)Whi;
        const int4* l4 = (const int4*)Wlo;
#pragma unroll
        for (int i = tid; i < 2048; i += 256) {
            int k = i >> 4, seg = i & 15;
            *(int4*)&wh[k * LDW + seg * 8] = h4[i];
            *(int4*)&wl[k * LDW + seg * 8] = l4[i];
        }
    }
    __syncthreads();

    const int w  = tid >> 5;
    const int wr = w >> 2;
    const int wc = w & 3;

    wmma::fragment<wmma::accumulator, 16, 16, 16, float> acc[2][2];
#pragma unroll
    for (int i = 0; i < 2; i++)
#pragma unroll
        for (int j = 0; j < 2; j++) wmma::fill_fragment(acc[i][j], 0.f);

#pragma unroll
    for (int ks = 0; ks < 8; ks++) {
        const int k0 = ks * 16;
        wmma::fragment<wmma::matrix_a, 16, 16, 16, __nv_bfloat16,
                       wmma::row_major> ah[2], al[2];
        wmma::fragment<wmma::matrix_b, 16, 16, 16, __nv_bfloat16,
                       wmma::row_major> bh[2], bl[2];
#pragma unroll
        for (int i = 0; i < 2; i++) {
            wmma::load_matrix_sync(ah[i], &xhi[(wr * 32 + i * 16) * LDX + k0], LDX);
            wmma::load_matrix_sync(al[i], &xlo[(wr * 32 + i * 16) * LDX + k0], LDX);
        }
#pragma unroll
        for (int j = 0; j < 2; j++) {
            wmma::load_matrix_sync(bh[j], &wh[k0 * LDW + wc * 32 + j * 16], LDW);
            wmma::load_matrix_sync(bl[j], &wl[k0 * LDW + wc * 32 + j * 16], LDW);
        }
#pragma unroll
        for (int i = 0; i < 2; i++)
#pragma unroll
            for (int j = 0; j < 2; j++) {
                wmma::mma_sync(acc[i][j], ah[i], bh[j], acc[i][j]);
                wmma::mma_sync(acc[i][j], ah[i], bl[j], acc[i][j]);
                wmma::mma_sync(acc[i][j], al[i], bh[j], acc[i][j]);
            }
    }

    __syncthreads();
    float* stage = (float*)smem;
#pragma unroll
    for (int i = 0; i < 2; i++)
#pragma unroll
        for (int j = 0; j < 2; j++) {
            wmma::store_matrix_sync(&stage[(wr * 32 + i * 16) * LDS
                                           + wc * 32 + j * 16],
                                    acc[i][j], LDS, wmma::mem_row_major);
        }
    __syncthreads();
    __half2* Y2 = (__half2*)Yh;
#pragma unroll
    for (int i = tid; i < 64 * 64; i += 256) {
        int r = i >> 6, c2 = i & 63;
        float a = stage[r * LDS + 2 * c2];
        float b = stage[r * LDS + 2 * c2 + 1];
        Y2[(size_t)(row0 + r) * 64 + c2] = __floats2half2_rn(a, b);
    }
}

// ---- layer-2 GEMM: fp16 X (exact) x fp16 W hi/lo, 2 passes ----------------
__global__ void gemm128_tc_h16_kernel(const __half* __restrict__ X16,
                                      const __half* __restrict__ Whi,
                                      const __half* __restrict__ Wlo,
                                      __half* __restrict__ Yh, int nrows) {
    extern __shared__ char smem[];
    __half* xs = (__half*)smem;          // 64 * LDX
    __half* wh = xs + 64 * LDX;          // 128 * LDW
    __half* wl = wh + 128 * LDW;
    const int tid = threadIdx.x;
    const int row0 = blockIdx.x * 64;

    {
        const uint2* X2 = (const uint2*)X16;
#pragma unroll
        for (int i = tid; i < 64 * 32; i += 256) {
            int r = i >> 5, kq = i & 31;
            uint2 u = make_uint2(0u, 0u);
            if (row0 + r < nrows) u = X2[(size_t)(row0 + r) * 32 + kq];
            *(uint2*)&xs[r * LDX + kq * 4] = u;
        }
    }
    {
        const int4* h4 = (const int4*)Whi;
        const int4* l4 = (const int4*)Wlo;
#pragma unroll
        for (int i = tid; i < 2048; i += 256) {
            int k = i >> 4, seg = i & 15;
            *(int4*)&wh[k * LDW + seg * 8] = h4[i];
            *(int4*)&wl[k * LDW + seg * 8] = l4[i];
        }
    }
    __syncthreads();

    const int w  = tid >> 5;
    const int wr = w >> 2;
    const int wc = w & 3;

    wmma::fragment<wmma::accumulator, 16, 16, 16, float> acc[2][2];
#pragma unroll
    for (int i = 0; i < 2; i++)
#pragma unroll
        for (int j = 0; j < 2; j++) wmma::fill_fragment(acc[i][j], 0.f);

#pragma unroll
    for (int ks = 0; ks < 8; ks++) {
        const int k0 = ks * 16;
        wmma::fragment<wmma::matrix_a, 16, 16, 16, __half,
                       wmma::row_major> a[2];
        wmma::fragment<wmma::matrix_b, 16, 16, 16, __half,
                       wmma::row_major> bh[2], bl[2];
#pragma unroll
        for (int i = 0; i < 2; i++)
            wmma::load_matrix_sync(a[i], &xs[(wr * 32 + i * 16) * LDX + k0], LDX);
#pragma unroll
        for (int j = 0; j < 2; j++) {
            wmma::load_matrix_sync(bh[j], &wh[k0 * LDW + wc * 32 + j * 16], LDW);
            wmma::load_matrix_sync(bl[j], &wl[k0 * LDW + wc * 32 + j * 16], LDW);
        }
#pragma unroll
        for (int i = 0; i < 2; i++)
#pragma unroll
            for (int j = 0; j < 2; j++) {
                wmma::mma_sync(acc[i][j], a[i], bh[j], acc[i][j]);
                wmma::mma_sync(acc[i][j], a[i], bl[j], acc[i][j]);
            }
    }

    __syncthreads();
    float* stage = (float*)smem;   // overlaps xs+wh (dead after mainloop)
#pragma unroll
    for (int i = 0; i < 2; i++)
#pragma unroll
        for (int j = 0; j < 2; j++) {
            wmma::store_matrix_sync(&stage[(wr * 32 + i * 16) * LDS
                                           + wc * 32 + j * 16],
                                    acc[i][j], LDS, wmma::mem_row_major);
        }
    __syncthreads();
    __half2* Y2 = (__half2*)Yh;
#pragma unroll
    for (int i = tid; i < 64 * 64; i += 256) {
        int r = i >> 6, c2 = i & 63;
        float a = stage[r * LDS + 2 * c2];
        float b = stage[r * LDS + 2 * c2 + 1];
        Y2[(size_t)(row0 + r) * 64 + c2] = __floats2half2_rn(a, b);
    }
}

// ---------------- SIMT GEMM, D_OUT=40 (fp16 in, fp16 out) ------------------
__global__ void gemm40_kernel(const __half* __restrict__ X16,
                              const float* __restrict__ W,
                              __half* __restrict__ Yh, int nrows) {
    extern __shared__ float sm[];
    float* Ws = sm;
    float* Xs = sm + 128 * DO;
    const int tid = threadIdx.x;

    for (int i = tid; i < 128 * DO; i += 320) Ws[i] = W[i];

    const int row0 = blockIdx.x * 64;
    const uint2* X2 = (const uint2*)X16;
    for (int i = tid; i < 64 * 32; i += 320) {
        int r = i >> 5, kq = i & 31;
        float4 v = make_float4(0.f, 0.f, 0.f, 0.f);
        if (row0 + r < nrows) {
            uint2 u = X2[(size_t)(row0 + r) * 32 + kq];
            float2 a = __half22float2(*(__half2*)&u.x);
            float2 b = __half22float2(*(__half2*)&u.y);
            v = make_float4(a.x, a.y, b.x, b.y);
        }
        *(float4*)&Xs[r * 128 + kq * 4] = v;
    }
    __syncthreads();

    const int c  = tid % DO;
    const int rg = tid / DO;
    float acc[8];
#pragma unroll
    for (int r = 0; r < 8; r++) acc[r] = 0.f;
    const float4* xb4 = (const float4*)(Xs + rg * 8 * 128);

#pragma unroll 4
    for (int k4 = 0; k4 < 32; k4++) {
        float w0 = Ws[(4 * k4 + 0) * DO + c];
        float w1 = Ws[(4 * k4 + 1) * DO + c];
        float w2 = Ws[(4 * k4 + 2) * DO + c];
        float w3 = Ws[(4 * k4 + 3) * DO + c];
#pragma unroll
        for (int r = 0; r < 8; r++) {
            float4 xv = xb4[r * 32 + k4];
            acc[r] += xv.x * w0 + xv.y * w1 + xv.z * w2 + xv.w * w3;
        }
    }
#pragma unroll
    for (int r = 0; r < 8; r++) {
        int gr = row0 + rg * 8 + r;
        if (gr < nrows) Yh[(size_t)gr * DO + c] = __float2half_rn(acc[r]);
    }
}

// ----------------------- CSR gather aggregation ----------------------------
__global__ void agg128_kernel(const int* __restrict__ rowptr,
                              const int2* __restrict__ epack,
                              const __half* __restrict__ H,
                              const float* __restrict__ bias,
                              __half* __restrict__ Y, int n) {
    int node = blockIdx.x * 8 + (threadIdx.x >> 5);
    if (node >= n) return;
    const int lane = threadIdx.x & 31;
    int beg = rowptr[node];
    int end = rowptr[node + 1];

    float4 acc = make_float4(0.f, 0.f, 0.f, 0.f);
    int j = beg;
    for (; j + 7 < end; j += 8) {
        int2 ed[8];
        uint2 u[8];
#pragma unroll
        for (int q = 0; q < 8; q++) ed[q] = epack[j + q];
#pragma unroll
        for (int q = 0; q < 8; q++)
            u[q] = ((const uint2*)(H + (size_t)ed[q].x * 128))[lane];
#pragma unroll
        for (int q = 0; q < 8; q++) {
            float w = __int_as_float(ed[q].y);
            float2 a = __half22float2(*(__half2*)&u[q].x);
            float2 b = __half22float2(*(__half2*)&u[q].y);
            acc.x += a.x * w; acc.y += a.y * w;
            acc.z += b.x * w; acc.w += b.y * w;
        }
    }
    for (; j < end; j++) {
        int2 e = epack[j];
        float w = __int_as_float(e.y);
        uint2 u = ((const uint2*)(H + (size_t)e.x * 128))[lane];
        float2 a = __half22float2(*(__half2*)&u.x);
        float2 b = __half22float2(*(__half2*)&u.y);
        acc.x += a.x * w; acc.y += a.y * w;
        acc.z += b.x * w; acc.w += b.y * w;
    }

    float4 b4 = ((const float4*)bias)[lane];
    acc.x = fmaxf(acc.x + b4.x, 0.f);
    acc.y = fmaxf(acc.y + b4.y, 0.f);
    acc.z = fmaxf(acc.z + b4.z, 0.f);
    acc.w = fmaxf(acc.w + b4.w, 0.f);
    __half2 h0 = __floats2half2_rn(acc.x, acc.y);
    __half2 h1 = __floats2half2_rn(acc.z, acc.w);
    uint2 o;
    o.x = *(uint32_t*)&h0;
    o.y = *(uint32_t*)&h1;
    ((uint2*)(Y + (size_t)node * 128))[lane] = o;
}

// D=40 gather (fp16 H) + bias + log_softmax, one warp per node, unroll 4.
__global__ void agg40_lsm_kernel(const int* __restrict__ rowptr,
                                 const int2* __restrict__ epack,
                                 const __half* __restrict__ H,
                                 const float* __restrict__ b,
                                 float* __restrict__ out, int n) {
    int node = blockIdx.x * 8 + (threadIdx.x >> 5);
    if (node >= n) return;
    const int lane = threadIdx.x & 31;
    int beg = rowptr[node];
    int end = rowptr[node + 1];

    float a0 = 0.f, a1 = 0.f;
    int j = beg;
    for (; j + 3 < end; j += 4) {
        int2 ed[4];
#pragma unroll
        for (int q = 0; q < 4; q++) ed[q] = epack[j + q];
        __half v0[4], v1[4];
#pragma unroll
        for (int q = 0; q < 4; q++) {
            const __half* hs = H + (size_t)ed[q].x * DO;
            v0[q] = hs[lane];
            v1[q] = (lane < 8) ? hs[32 + lane] : __half(0.f);
        }
#pragma unroll
        for (int q = 0; q < 4; q++) {
            float w = __int_as_float(ed[q].y);
            a0 += __half2float(v0[q]) * w;
            a1 += __half2float(v1[q]) * w;
        }
    }
    for (; j < end; j++) {
        int2 e = epack[j];
        float w = __int_as_float(e.y);
        const __half* hs = H + (size_t)e.x * DO;
        a0 += __half2float(hs[lane]) * w;
        if (lane < 8) a1 += __half2float(hs[32 + lane]) * w;
    }

    float v0 = a0 + b[lane];
    float v1 = (lane < 8) ? (a1 + b[32 + lane]) : -1e30f;

    float m = fmaxf(v0, v1);
#pragma unroll
    for (int o = 16; o; o >>= 1) m = fmaxf(m, __shfl_xor_sync(0xffffffffu, m, o));

    float sum = __expf(v0 - m) + ((lane < 8) ? __expf(v1 - m) : 0.f);
#pragma unroll
    for (int o = 16; o; o >>= 1) sum += __shfl_xor_sync(0xffffffffu, sum, o);

    float lse = m + __logf(sum);
    out[(size_t)node * DO + lane] = v0 - lse;
    if (lane < 8) out[(size_t)node * DO + 32 + lane] = v1 - lse;
}

// ---------------------------------------------------------------------------
extern "C" void kernel_launch(void* const* d_in, const int* in_sizes, int n_in,
                              void* d_out, int out_size) {
    const float* x  = (const float*)d_in[0];
    const void*  ei = d_in[1];
    const float* ew = (const float*)d_in[2];
    const float* W1 = (const float*)d_in[3];
    const float* b1 = (const float*)d_in[4];
    const float* W2 = (const float*)d_in[5];
    const float* b2 = (const float*)d_in[6];
    const float* W3 = (const float*)d_in[7];
    const float* b3 = (const float*)d_in[8];
    float* out = (float*)d_out;

    const int n  = in_sizes[0] / DH;
    int ne = in_sizes[1] / 2;
    if (ne > MAXE) ne = MAXE;
    (void)n_in; (void)out_size;

    float *A, *B;
    int *rowptr, *deg, *fill, *partials;
    int2* epack;
    __nv_bfloat16 *w1hi, *w1lo;
    __half *w2hi, *w2lo;
    cudaGetSymbolAddress((void**)&A, g_bufA);
    cudaGetSymbolAddress((void**)&B, g_bufB);
    cudaGetSymbolAddress((void**)&rowptr, g_rowptr);
    cudaGetSymbolAddress((void**)&deg, g_deg);
    cudaGetSymbolAddress((void**)&fill, g_fill);
    cudaGetSymbolAddress((void**)&epack, g_epack);
    cudaGetSymbolAddress((void**)&partials, g_partials);
    cudaGetSymbolAddress((void**)&w1hi, g_w1hi);
    cudaGetSymbolAddress((void**)&w1lo, g_w1lo);
    cudaGetSymbolAddress((void**)&w2hi, g_w2hi);
    cudaGetSymbolAddress((void**)&w2lo, g_w2lo);

    __half* Ah = (__half*)A;
    __half* Bh = (__half*)B;

    const int SMEM_TC  = (2 * 64 * LDX + 2 * 128 * LDW) * (int)sizeof(__nv_bfloat16);
    const int SMEM_TCH = (64 * LDX + 2 * 128 * LDW) * (int)sizeof(__half);
    const int SMEM40   = (128 * DO + 64 * 128) * (int)sizeof(float);
    cudaFuncSetAttribute(gemm128_tc_kernel,
                         cudaFuncAttributeMaxDynamicSharedMemorySize, SMEM_TC);
    cudaFuncSetAttribute(gemm128_tc_h16_kernel,
                         cudaFuncAttributeMaxDynamicSharedMemorySize, SMEM_TCH);
    cudaFuncSetAttribute(gemm40_kernel,
                         cudaFuncAttributeMaxDynamicSharedMemorySize, SMEM40);

    const int tcBlocks       = (n + 63) / 64;
    const int nodeWarpBlocks = (n + 7) / 8;
    const int scanBlocks     = (n + 1023) / 1024;
    const int edge2Blocks    = ((ne + 1) / 2 + 255) / 256;

    static cudaStream_t s2 = nullptr;
    static cudaEvent_t evFork = nullptr, evJoin = nullptr;
    if (s2 == nullptr) {
        cudaStreamCreateWithFlags(&s2, cudaStreamNonBlocking);
        cudaEventCreateWithFlags(&evFork, cudaEventDisableTiming);
        cudaEventCreateWithFlags(&evJoin, cudaEventDisableTiming);
    }

    // ---- fork: CSR build on side stream ----
    cudaEventRecord(evFork, 0);
    cudaStreamWaitEvent(s2, evFork, 0);
    deg_zero_kernel<<<(n + 255) / 256, 256, 0, s2>>>(deg, n, ei, n);
    deg_count_kernel<<<edge2Blocks, 256, 0, s2>>>(ei, ne, deg);
    scan_block_kernel<<<scanBlocks, 1024, 0, s2>>>(deg, rowptr, partials, n);
    scan_partials_kernel<<<1, 128, 0, s2>>>(partials, scanBlocks);
    scan_add_kernel<<<(n + 255) / 256, 256, 0, s2>>>(rowptr, partials, fill, n, ne);
    csr_fill_kernel<<<edge2Blocks, 256, 0, s2>>>(ei, ew, ne, fill, epack);
    cudaEventRecord(evJoin, s2);

    // ---- main stream: W prep + layer-1 GEMM overlap the CSR build ----
    prep_w2_kernel<<<128, 256>>>(W1, w1hi, w1lo, W2, w2hi, w2lo);
    gemm128_tc_kernel<<<tcBlocks, 256, SMEM_TC>>>(x, w1hi, w1lo, Ah, n);

    // ---- join ----
    cudaStreamWaitEvent(0, evJoin, 0);

    // ---- layer 1 ----
    agg128_kernel<<<nodeWarpBlocks, 256>>>(rowptr, epack, Ah, b1, Bh, n);
    // ---- layer 2 (fp16 x fp16 hi/lo, 2 passes) ----
    gemm128_tc_h16_kernel<<<tcBlocks, 256, SMEM_TCH>>>(Bh, w2hi, w2lo, Ah, n);
    agg128_kernel<<<nodeWarpBlocks, 256>>>(rowptr, epack, Ah, b2, Bh, n);
    // ---- layer 3 (D_OUT = 40) ----
    gemm40_kernel<<<tcBlocks, 320, SMEM40>>>(Bh, W3, Ah, n);
    agg40_lsm_kernel<<<nodeWarpBlocks, 256>>>(rowptr, epack, Ah, b3, out, n);
}

// round 16
// speedup vs baseline: 1.4939x; 1.1636x over previous
#include <cuda_runtime.h>
#include <cuda_bf16.h>
#include <cuda_fp16.h>
#include <mma.h>
#include <cstdint>

using namespace nvcuda;

// ---------------------------------------------------------------------------
// AdjGCN: 3-layer GCN forward.
//  - CSR-gather aggregation; CSR built on a forked stream; int2 edge payload.
//  - L1 GEMM: bf16x3 wmma (fp32 X). L2 GEMM: fp16 X x fp16 W hi/lo (2-pass).
//  - L3 GEMM (D_OUT=40): wmma, fp16 X x fp16 W3 hi/lo padded to N=48.
//  - ALL inter-layer tensors fp16; all accumulation fp32.
// ---------------------------------------------------------------------------

#define MAXN 100000
#define MAXNP 100096
#define MAXE 1600000
#define DH   128
#define DO   40
#define NO3  48      // padded N for the wmma D_OUT=40 gemm
#define LDX  136
#define LDW  136
#define LDW3 56
#define LDS  132
#define LDS3 52

__device__ float         g_bufA[(size_t)MAXNP * DH];   // fp16 H (gemm outs)
__device__ float         g_bufB[(size_t)MAXNP * DH];   // fp16 agg outs
__device__ int           g_idx64;
__device__ int           g_rowptr[MAXN + 1];
__device__ int           g_deg[MAXN];
__device__ int           g_fill[MAXN];
__device__ int2          g_epack[MAXE];
__device__ int           g_partials[128];
__device__ __nv_bfloat16 g_w1hi[128 * 128];
__device__ __nv_bfloat16 g_w1lo[128 * 128];
__device__ __half        g_w2hi[128 * 128];
__device__ __half        g_w2lo[128 * 128];
__device__ __half        g_w3hi[128 * NO3];
__device__ __half        g_w3lo[128 * NO3];

// ------------------------------ CSR build ---------------------------------
__global__ void deg_zero_kernel(int* __restrict__ deg, int n,
                                const void* ei, int n_nodes) {
    int i = blockIdx.x * blockDim.x + threadIdx.x;
    if (i < n) deg[i] = 0;
    if (blockIdx.x == 0 && threadIdx.x == 0) {
        const long long* p = (const long long*)ei;
        int ok64 = 1;
        for (int k = 0; k < 32; k++) {
            long long v = p[k];
            if (v < 0 || v >= n_nodes) { ok64 = 0; break; }
        }
        g_idx64 = ok64;
    }
}

__global__ void deg_count_kernel(const void* __restrict__ ei, int ne,
                                 int* __restrict__ deg) {
    int e = (blockIdx.x * blockDim.x + threadIdx.x) * 2;
    if (e >= ne) return;
    int d0, d1 = -1;
    if (g_idx64) {
        const long long* p = (const long long*)ei + ne;
        if (e + 1 < ne) {
            longlong2 v = *(const longlong2*)(p + e);
            d0 = (int)v.x; d1 = (int)v.y;
        } else d0 = (int)p[e];
    } else {
        const int* p = (const int*)ei + ne;
        if (e + 1 < ne) {
            int2 v = *(const int2*)(p + e);
            d0 = v.x; d1 = v.y;
        } else d0 = p[e];
    }
    atomicAdd(&deg[d0], 1);
    if (d1 >= 0) atomicAdd(&deg[d1], 1);
}

__global__ void scan_block_kernel(const int* __restrict__ deg,
                                  int* __restrict__ rowptr,
                                  int* __restrict__ partials, int n) {
    __shared__ int sm[1024];
    const int tid = threadIdx.x;
    int i = blockIdx.x * 1024 + tid;
    int v = (i < n) ? deg[i] : 0;
    sm[tid] = v;
    __syncthreads();
#pragma unroll
    for (int o = 1; o < 1024; o <<= 1) {
        int t = (tid >= o) ? sm[tid - o] : 0;
        __syncthreads();
        sm[tid] += t;
        __syncthreads();
    }
    if (i < n) rowptr[i] = sm[tid] - v;
    if (tid == 1023) partials[blockIdx.x] = sm[1023];
}

__global__ void scan_partials_kernel(int* __restrict__ partials, int nb) {
    __shared__ int sm[128];
    const int tid = threadIdx.x;
    int v = (tid < nb) ? partials[tid] : 0;
    sm[tid] = v;
    __syncthreads();
#pragma unroll
    for (int o = 1; o < 128; o <<= 1) {
        int t = (tid >= o) ? sm[tid - o] : 0;
        __syncthreads();
        sm[tid] += t;
        __syncthreads();
    }
    if (tid < nb) partials[tid] = sm[tid] - v;
}

__global__ void scan_add_kernel(int* __restrict__ rowptr,
                                const int* __restrict__ partials,
                                int* __restrict__ fill, int n, int ne) {
    int i = blockIdx.x * blockDim.x + threadIdx.x;
    if (i < n) {
        int v = rowptr[i] + partials[i >> 10];
        rowptr[i] = v;
        fill[i] = v;
    }
    if (i == 0) rowptr[n] = ne;
}

__global__ void csr_fill_kernel(const void* __restrict__ ei,
                                const float* __restrict__ ew, int ne,
                                int* __restrict__ fill,
                                int2* __restrict__ epack) {
    int e = (blockIdx.x * blockDim.x + threadIdx.x) * 2;
    if (e >= ne) return;
    int s0, d0, s1 = -1, d1 = -1;
    float w0, w1 = 0.f;
    if (g_idx64) {
        const long long* ps = (const long long*)ei;
        const long long* pd = ps + ne;
        if (e + 1 < ne) {
            longlong2 sv = *(const longlong2*)(ps + e);
            longlong2 dv = *(const longlong2*)(pd + e);
            float2 wv = *(const float2*)(ew + e);
            s0 = (int)sv.x; s1 = (int)sv.y;
            d0 = (int)dv.x; d1 = (int)dv.y;
            w0 = wv.x; w1 = wv.y;
        } else { s0 = (int)ps[e]; d0 = (int)pd[e]; w0 = ew[e]; }
    } else {
        const int* ps = (const int*)ei;
        const int* pd = ps + ne;
        if (e + 1 < ne) {
            int2 sv = *(const int2*)(ps + e);
            int2 dv = *(const int2*)(pd + e);
            float2 wv = *(const float2*)(ew + e);
            s0 = sv.x; s1 = sv.y; d0 = dv.x; d1 = dv.y;
            w0 = wv.x; w1 = wv.y;
        } else { s0 = ps[e]; d0 = pd[e]; w0 = ew[e]; }
    }
    int p0 = atomicAdd(&fill[d0], 1);
    epack[p0] = make_int2(s0, __float_as_int(w0));
    if (s1 >= 0) {
        int p1 = atomicAdd(&fill[d1], 1);
        epack[p1] = make_int2(s1, __float_as_int(w1));
    }
}

// ---- W prep: W1 -> bf16 hi/lo; W2 -> fp16 hi/lo; W3 -> fp16 hi/lo (N=48) --
__global__ void prep_w3_kernel(const float* __restrict__ Wa,
                               __nv_bfloat16* __restrict__ ahi,
                               __nv_bfloat16* __restrict__ alo,
                               const float* __restrict__ Wb,
                               __half* __restrict__ bhi,
                               __half* __restrict__ blo,
                               const float* __restrict__ Wc,
                               __half* __restrict__ chi,
                               __half* __restrict__ clo) {
    int i = blockIdx.x * blockDim.x + threadIdx.x;
    if (i < 128 * 128) {
        float w = Wa[i];
        __nv_bfloat16 h = __float2bfloat16_rn(w);
        ahi[i] = h;
        alo[i] = __float2bfloat16_rn(w - __bfloat162float(h));
    } else if (i < 2 * 128 * 128) {
        int k = i - 128 * 128;
        float w = Wb[k];
        __half h = __float2half_rn(w);
        bhi[k] = h;
        blo[k] = __float2half_rn(w - __half2float(h));
    } else if (i < 2 * 128 * 128 + 128 * NO3) {
        int k = i - 2 * 128 * 128;
        int row = k / NO3, col = k % NO3;
        float w = (col < DO) ? Wc[row * DO + col] : 0.f;
        __half h = __float2half_rn(w);
        chi[k] = h;
        clo[k] = __float2half_rn(w - __half2float(h));
    }
}

// ------------------ bf16 hi/lo packing helpers -----------------------------
__device__ __forceinline__ uint64_t pack4_hi(float a, float b, float c, float d) {
    __nv_bfloat162 p0 = __floats2bfloat162_rn(a, b);
    __nv_bfloat162 p1 = __floats2bfloat162_rn(c, d);
    return (uint64_t)(*(uint32_t*)&p0) | ((uint64_t)(*(uint32_t*)&p1) << 32);
}
__device__ __forceinline__ uint64_t pack4_lo(float a, float b, float c, float d) {
    float ah = __bfloat162float(__float2bfloat16_rn(a));
    float bh = __bfloat162float(__float2bfloat16_rn(b));
    float ch = __bfloat162float(__float2bfloat16_rn(c));
    float dh = __bfloat162float(__float2bfloat16_rn(d));
    __nv_bfloat162 p0 = __floats2bfloat162_rn(a - ah, b - bh);
    __nv_bfloat162 p1 = __floats2bfloat162_rn(c - ch, d - dh);
    return (uint64_t)(*(uint32_t*)&p0) | ((uint64_t)(*(uint32_t*)&p1) << 32);
}

// ---------- layer-1 GEMM: fp32 X -> bf16x3 wmma -> fp16 H ------------------
__global__ void gemm128_tc_kernel(const float* __restrict__ X,
                                  const __nv_bfloat16* __restrict__ Whi,
                                  const __nv_bfloat16* __restrict__ Wlo,
                                  __half* __restrict__ Yh, int nrows) {
    extern __shared__ char smem[];
    __nv_bfloat16* xhi = (__nv_bfloat16*)smem;
    __nv_bfloat16* xlo = xhi + 64 * LDX;
    __nv_bfloat16* wh  = xlo + 64 * LDX;
    __nv_bfloat16* wl  = wh + 128 * LDW;
    const int tid = threadIdx.x;
    const int row0 = blockIdx.x * 64;

    {
        const float4* X4 = (const float4*)X;
#pragma unroll
        for (int i = tid; i < 64 * 32; i += 256) {
            int r = i >> 5, kq = i & 31;
            float4 v = (row0 + r < nrows)
                           ? X4[(size_t)(row0 + r) * 32 + kq]
                           : make_float4(0.f, 0.f, 0.f, 0.f);
            *(uint64_t*)&xhi[r * LDX + kq * 4] = pack4_hi(v.x, v.y, v.z, v.w);
            *(uint64_t*)&xlo[r * LDX + kq * 4] = pack4_lo(v.x, v.y, v.z, v.w);
        }
    }
    {
        const int4* h4 = (const int4*)Whi;
        const int4* l4 = (const int4*)Wlo;
#pragma unroll
        for (int i = tid; i < 2048; i += 256) {
            int k = i >> 4, seg = i & 15;
            *(int4*)&wh[k * LDW + seg * 8] = h4[i];
            *(int4*)&wl[k * LDW + seg * 8] = l4[i];
        }
    }
    __syncthreads();

    const int w  = tid >> 5;
    const int wr = w >> 2;
    const int wc = w & 3;

    wmma::fragment<wmma::accumulator, 16, 16, 16, float> acc[2][2];
#pragma unroll
    for (int i = 0; i < 2; i++)
#pragma unroll
        for (int j = 0; j < 2; j++) wmma::fill_fragment(acc[i][j], 0.f);

#pragma unroll
    for (int ks = 0; ks < 8; ks++) {
        const int k0 = ks * 16;
        wmma::fragment<wmma::matrix_a, 16, 16, 16, __nv_bfloat16,
                       wmma::row_major> ah[2], al[2];
        wmma::fragment<wmma::matrix_b, 16, 16, 16, __nv_bfloat16,
                       wmma::row_major> bh[2], bl[2];
#pragma unroll
        for (int i = 0; i < 2; i++) {
            wmma::load_matrix_sync(ah[i], &xhi[(wr * 32 + i * 16) * LDX + k0], LDX);
            wmma::load_matrix_sync(al[i], &xlo[(wr * 32 + i * 16) * LDX + k0], LDX);
        }
#pragma unroll
        for (int j = 0; j < 2; j++) {
            wmma::load_matrix_sync(bh[j], &wh[k0 * LDW + wc * 32 + j * 16], LDW);
            wmma::load_matrix_sync(bl[j], &wl[k0 * LDW + wc * 32 + j * 16], LDW);
        }
#pragma unroll
        for (int i = 0; i < 2; i++)
#pragma unroll
            for (int j = 0; j < 2; j++) {
                wmma::mma_sync(acc[i][j], ah[i], bh[j], acc[i][j]);
                wmma::mma_sync(acc[i][j], ah[i], bl[j], acc[i][j]);
                wmma::mma_sync(acc[i][j], al[i], bh[j], acc[i][j]);
            }
    }

    __syncthreads();
    float* stage = (float*)smem;
#pragma unroll
    for (int i = 0; i < 2; i++)
#pragma unroll
        for (int j = 0; j < 2; j++) {
            wmma::store_matrix_sync(&stage[(wr * 32 + i * 16) * LDS
                                           + wc * 32 + j * 16],
                                    acc[i][j], LDS, wmma::mem_row_major);
        }
    __syncthreads();
    __half2* Y2 = (__half2*)Yh;
#pragma unroll
    for (int i = tid; i < 64 * 64; i += 256) {
        int r = i >> 6, c2 = i & 63;
        float a = stage[r * LDS + 2 * c2];
        float b = stage[r * LDS + 2 * c2 + 1];
        Y2[(size_t)(row0 + r) * 64 + c2] = __floats2half2_rn(a, b);
    }
}

// ---- layer-2 GEMM: fp16 X (exact) x fp16 W hi/lo, 2 passes ----------------
__global__ void gemm128_tc_h16_kernel(const __half* __restrict__ X16,
                                      const __half* __restrict__ Whi,
                                      const __half* __restrict__ Wlo,
                                      __half* __restrict__ Yh, int nrows) {
    extern __shared__ char smem[];
    __half* xs = (__half*)smem;          // 64 * LDX
    __half* wh = xs + 64 * LDX;          // 128 * LDW
    __half* wl = wh + 128 * LDW;
    const int tid = threadIdx.x;
    const int row0 = blockIdx.x * 64;

    {
        const uint2* X2 = (const uint2*)X16;
#pragma unroll
        for (int i = tid; i < 64 * 32; i += 256) {
            int r = i >> 5, kq = i & 31;
            uint2 u = make_uint2(0u, 0u);
            if (row0 + r < nrows) u = X2[(size_t)(row0 + r) * 32 + kq];
            *(uint2*)&xs[r * LDX + kq * 4] = u;
        }
    }
    {
        const int4* h4 = (const int4*)Whi;
        const int4* l4 = (const int4*)Wlo;
#pragma unroll
        for (int i = tid; i < 2048; i += 256) {
            int k = i >> 4, seg = i & 15;
            *(int4*)&wh[k * LDW + seg * 8] = h4[i];
            *(int4*)&wl[k * LDW + seg * 8] = l4[i];
        }
    }
    __syncthreads();

    const int w  = tid >> 5;
    const int wr = w >> 2;
    const int wc = w & 3;

    wmma::fragment<wmma::accumulator, 16, 16, 16, float> acc[2][2];
#pragma unroll
    for (int i = 0; i < 2; i++)
#pragma unroll
        for (int j = 0; j < 2; j++) wmma::fill_fragment(acc[i][j], 0.f);

#pragma unroll
    for (int ks = 0; ks < 8; ks++) {
        const int k0 = ks * 16;
        wmma::fragment<wmma::matrix_a, 16, 16, 16, __half,
                       wmma::row_major> a[2];
        wmma::fragment<wmma::matrix_b, 16, 16, 16, __half,
                       wmma::row_major> bh[2], bl[2];
#pragma unroll
        for (int i = 0; i < 2; i++)
            wmma::load_matrix_sync(a[i], &xs[(wr * 32 + i * 16) * LDX + k0], LDX);
#pragma unroll
        for (int j = 0; j < 2; j++) {
            wmma::load_matrix_sync(bh[j], &wh[k0 * LDW + wc * 32 + j * 16], LDW);
            wmma::load_matrix_sync(bl[j], &wl[k0 * LDW + wc * 32 + j * 16], LDW);
        }
#pragma unroll
        for (int i = 0; i < 2; i++)
#pragma unroll
            for (int j = 0; j < 2; j++) {
                wmma::mma_sync(acc[i][j], a[i], bh[j], acc[i][j]);
                wmma::mma_sync(acc[i][j], a[i], bl[j], acc[i][j]);
            }
    }

    __syncthreads();
    float* stage = (float*)smem;
#pragma unroll
    for (int i = 0; i < 2; i++)
#pragma unroll
        for (int j = 0; j < 2; j++) {
            wmma::store_matrix_sync(&stage[(wr * 32 + i * 16) * LDS
                                           + wc * 32 + j * 16],
                                    acc[i][j], LDS, wmma::mem_row_major);
        }
    __syncthreads();
    __half2* Y2 = (__half2*)Yh;
#pragma unroll
    for (int i = tid; i < 64 * 64; i += 256) {
        int r = i >> 6, c2 = i & 63;
        float a = stage[r * LDS + 2 * c2];
        float b = stage[r * LDS + 2 * c2 + 1];
        Y2[(size_t)(row0 + r) * 64 + c2] = __floats2half2_rn(a, b);
    }
}

// ---- layer-3 GEMM (D_OUT=40): fp16 X x fp16 W3 hi/lo, N padded to 48 ------
// 256 threads; 6 of 8 warps own a 32x16 tile: wr=w&1 (row half), wc=w>>1<3.
__global__ void gemm40_tc_kernel(const __half* __restrict__ X16,
                                 const __half* __restrict__ Whi,
                                 const __half* __restrict__ Wlo,
                                 __half* __restrict__ Yh, int nrows) {
    extern __shared__ char smem[];
    __half* xs = (__half*)smem;          // 64 * LDX
    __half* wh = xs + 64 * LDX;          // 128 * LDW3
    __half* wl = wh + 128 * LDW3;
    const int tid = threadIdx.x;
    const int row0 = blockIdx.x * 64;

    {
        const uint2* X2 = (const uint2*)X16;
#pragma unroll
        for (int i = tid; i < 64 * 32; i += 256) {
            int r = i >> 5, kq = i & 31;
            uint2 u = make_uint2(0u, 0u);
            if (row0 + r < nrows) u = X2[(size_t)(row0 + r) * 32 + kq];
            *(uint2*)&xs[r * LDX + kq * 4] = u;
        }
    }
    {
        const int4* h4 = (const int4*)Whi;   // 128*48 halves = 768 int4
        const int4* l4 = (const int4*)Wlo;
#pragma unroll
        for (int i = tid; i < 768; i += 256) {
            int k = i / 6, seg = i % 6;
            *(int4*)&wh[k * LDW3 + seg * 8] = h4[i];
            *(int4*)&wl[k * LDW3 + seg * 8] = l4[i];
        }
    }
    __syncthreads();

    const int w  = tid >> 5;
    const int wr = w & 1;       // row half: rows wr*32..+31
    const int wc = w >> 1;      // col tile: cols wc*16..+15 (active wc<3)

    if (wc < 3) {
        wmma::fragment<wmma::accumulator, 16, 16, 16, float> acc[2];
#pragma unroll
        for (int i = 0; i < 2; i++) wmma::fill_fragment(acc[i], 0.f);

#pragma unroll
        for (int ks = 0; ks < 8; ks++) {
            const int k0 = ks * 16;
            wmma::fragment<wmma::matrix_a, 16, 16, 16, __half,
                           wmma::row_major> a[2];
            wmma::fragment<wmma::matrix_b, 16, 16, 16, __half,
                           wmma::row_major> bh, bl;
#pragma unroll
            for (int i = 0; i < 2; i++)
                wmma::load_matrix_sync(a[i], &xs[(wr * 32 + i * 16) * LDX + k0], LDX);
            wmma::load_matrix_sync(bh, &wh[k0 * LDW3 + wc * 16], LDW3);
            wmma::load_matrix_sync(bl, &wl[k0 * LDW3 + wc * 16], LDW3);
#pragma unroll
            for (int i = 0; i < 2; i++) {
                wmma::mma_sync(acc[i], a[i], bh, acc[i]);
                wmma::mma_sync(acc[i], a[i], bl, acc[i]);
            }
        }

        __syncthreads();
        float* stage = (float*)smem;
#pragma unroll
        for (int i = 0; i < 2; i++)
            wmma::store_matrix_sync(&stage[(wr * 32 + i * 16) * LDS3 + wc * 16],
                                    acc[i], LDS3, wmma::mem_row_major);
    } else {
        __syncthreads();
    }
    __syncthreads();
    // write 64 rows x 40 cols fp16 (20 half2 per row)
    float* stage = (float*)smem;
    __half2* Y2 = (__half2*)Yh;
#pragma unroll
    for (int i = tid; i < 64 * 20; i += 256) {
        int r = i / 20, c2 = i % 20;
        float a = stage[r * LDS3 + 2 * c2];
        float b = stage[r * LDS3 + 2 * c2 + 1];
        Y2[(size_t)(row0 + r) * 20 + c2] = __floats2half2_rn(a, b);
    }
}

// ----------------------- CSR gather aggregation ----------------------------
__global__ void agg128_kernel(const int* __restrict__ rowptr,
                              const int2* __restrict__ epack,
                              const __half* __restrict__ H,
                              const float* __restrict__ bias,
                              __half* __restrict__ Y, int n) {
    int node = blockIdx.x * 8 + (threadIdx.x >> 5);
    if (node >= n) return;
    const int lane = threadIdx.x & 31;
    int beg = rowptr[node];
    int end = rowptr[node + 1];

    float4 acc = make_float4(0.f, 0.f, 0.f, 0.f);
    int j = beg;
    for (; j + 7 < end; j += 8) {
        int2 ed[8];
        uint2 u[8];
#pragma unroll
        for (int q = 0; q < 8; q++) ed[q] = epack[j + q];
#pragma unroll
        for (int q = 0; q < 8; q++)
            u[q] = ((const uint2*)(H + (size_t)ed[q].x * 128))[lane];
#pragma unroll
        for (int q = 0; q < 8; q++) {
            float w = __int_as_float(ed[q].y);
            float2 a = __half22float2(*(__half2*)&u[q].x);
            float2 b = __half22float2(*(__half2*)&u[q].y);
            acc.x += a.x * w; acc.y += a.y * w;
            acc.z += b.x * w; acc.w += b.y * w;
        }
    }
    for (; j < end; j++) {
        int2 e = epack[j];
        float w = __int_as_float(e.y);
        uint2 u = ((const uint2*)(H + (size_t)e.x * 128))[lane];
        float2 a = __half22float2(*(__half2*)&u.x);
        float2 b = __half22float2(*(__half2*)&u.y);
        acc.x += a.x * w; acc.y += a.y * w;
        acc.z += b.x * w; acc.w += b.y * w;
    }

    float4 b4 = ((const float4*)bias)[lane];
    acc.x = fmaxf(acc.x + b4.x, 0.f);
    acc.y = fmaxf(acc.y + b4.y, 0.f);
    acc.z = fmaxf(acc.z + b4.z, 0.f);
    acc.w = fmaxf(acc.w + b4.w, 0.f);
    __half2 h0 = __floats2half2_rn(acc.x, acc.y);
    __half2 h1 = __floats2half2_rn(acc.z, acc.w);
    uint2 o;
    o.x = *(uint32_t*)&h0;
    o.y = *(uint32_t*)&h1;
    ((uint2*)(Y + (size_t)node * 128))[lane] = o;
}

// D=40 gather (fp16 H) + bias + log_softmax, one warp per node, unroll 4.
__global__ void agg40_lsm_kernel(const int* __restrict__ rowptr,
                                 const int2* __restrict__ epack,
                                 const __half* __restrict__ H,
                                 const float* __restrict__ b,
                                 float* __restrict__ out, int n) {
    int node = blockIdx.x * 8 + (threadIdx.x >> 5);
    if (node >= n) return;
    const int lane = threadIdx.x & 31;
    int beg = rowptr[node];
    int end = rowptr[node + 1];

    float a0 = 0.f, a1 = 0.f;
    int j = beg;
    for (; j + 3 < end; j += 4) {
        int2 ed[4];
#pragma unroll
        for (int q = 0; q < 4; q++) ed[q] = epack[j + q];
        __half v0[4], v1[4];
#pragma unroll
        for (int q = 0; q < 4; q++) {
            const __half* hs = H + (size_t)ed[q].x * DO;
            v0[q] = hs[lane];
            v1[q] = (lane < 8) ? hs[32 + lane] : __half(0.f);
        }
#pragma unroll
        for (int q = 0; q < 4; q++) {
            float w = __int_as_float(ed[q].y);
            a0 += __half2float(v0[q]) * w;
            a1 += __half2float(v1[q]) * w;
        }
    }
    for (; j < end; j++) {
        int2 e = epack[j];
        float w = __int_as_float(e.y);
        const __half* hs = H + (size_t)e.x * DO;
        a0 += __half2float(hs[lane]) * w;
        if (lane < 8) a1 += __half2float(hs[32 + lane]) * w;
    }

    float v0 = a0 + b[lane];
    float v1 = (lane < 8) ? (a1 + b[32 + lane]) : -1e30f;

    float m = fmaxf(v0, v1);
#pragma unroll
    for (int o = 16; o; o >>= 1) m = fmaxf(m, __shfl_xor_sync(0xffffffffu, m, o));

    float sum = __expf(v0 - m) + ((lane < 8) ? __expf(v1 - m) : 0.f);
#pragma unroll
    for (int o = 16; o; o >>= 1) sum += __shfl_xor_sync(0xffffffffu, sum, o);

    float lse = m + __logf(sum);
    out[(size_t)node * DO + lane] = v0 - lse;
    if (lane < 8) out[(size_t)node * DO + 32 + lane] = v1 - lse;
}

// ---------------------------------------------------------------------------
extern "C" void kernel_launch(void* const* d_in, const int* in_sizes, int n_in,
                              void* d_out, int out_size) {
    const float* x  = (const float*)d_in[0];
    const void*  ei = d_in[1];
    const float* ew = (const float*)d_in[2];
    const float* W1 = (const float*)d_in[3];
    const float* b1 = (const float*)d_in[4];
    const float* W2 = (const float*)d_in[5];
    const float* b2 = (const float*)d_in[6];
    const float* W3 = (const float*)d_in[7];
    const float* b3 = (const float*)d_in[8];
    float* out = (float*)d_out;

    const int n  = in_sizes[0] / DH;
    int ne = in_sizes[1] / 2;
    if (ne > MAXE) ne = MAXE;
    (void)n_in; (void)out_size;

    float *A, *B;
    int *rowptr, *deg, *fill, *partials;
    int2* epack;
    __nv_bfloat16 *w1hi, *w1lo;
    __half *w2hi, *w2lo, *w3hi, *w3lo;
    cudaGetSymbolAddress((void**)&A, g_bufA);
    cudaGetSymbolAddress((void**)&B, g_bufB);
    cudaGetSymbolAddress((void**)&rowptr, g_rowptr);
    cudaGetSymbolAddress((void**)&deg, g_deg);
    cudaGetSymbolAddress((void**)&fill, g_fill);
    cudaGetSymbolAddress((void**)&epack, g_epack);
    cudaGetSymbolAddress((void**)&partials, g_partials);
    cudaGetSymbolAddress((void**)&w1hi, g_w1hi);
    cudaGetSymbolAddress((void**)&w1lo, g_w1lo);
    cudaGetSymbolAddress((void**)&w2hi, g_w2hi);
    cudaGetSymbolAddress((void**)&w2lo, g_w2lo);
    cudaGetSymbolAddress((void**)&w3hi, g_w3hi);
    cudaGetSymbolAddress((void**)&w3lo, g_w3lo);

    __half* Ah = (__half*)A;
    __half* Bh = (__half*)B;

    const int SMEM_TC   = (2 * 64 * LDX + 2 * 128 * LDW) * (int)sizeof(__nv_bfloat16);
    const int SMEM_TCH  = (64 * LDX + 2 * 128 * LDW) * (int)sizeof(__half);
    const int SMEM_TC40 = (64 * LDX + 2 * 128 * LDW3) * (int)sizeof(__half);
    cudaFuncSetAttribute(gemm128_tc_kernel,
                         cudaFuncAttributeMaxDynamicSharedMemorySize, SMEM_TC);
    cudaFuncSetAttribute(gemm128_tc_h16_kernel,
                         cudaFuncAttributeMaxDynamicSharedMemorySize, SMEM_TCH);
    cudaFuncSetAttribute(gemm40_tc_kernel,
                         cudaFuncAttributeMaxDynamicSharedMemorySize, SMEM_TC40);

    const int tcBlocks       = (n + 63) / 64;
    const int nodeWarpBlocks = (n + 7) / 8;
    const int scanBlocks     = (n + 1023) / 1024;
    const int edge2Blocks    = ((ne + 1) / 2 + 255) / 256;

    static cudaStream_t s2 = nullptr;
    static cudaEvent_t evFork = nullptr, evJoin = nullptr;
    if (s2 == nullptr) {
        cudaStreamCreateWithFlags(&s2, cudaStreamNonBlocking);
        cudaEventCreateWithFlags(&evFork, cudaEventDisableTiming);
        cudaEventCreateWithFlags(&evJoin, cudaEventDisableTiming);
    }

    // ---- fork: CSR build on side stream ----
    cudaEventRecord(evFork, 0);
    cudaStreamWaitEvent(s2, evFork, 0);
    deg_zero_kernel<<<(n + 255) / 256, 256, 0, s2>>>(deg, n, ei, n);
    deg_count_kernel<<<edge2Blocks, 256, 0, s2>>>(ei, ne, deg);
    scan_block_kernel<<<scanBlocks, 1024, 0, s2>>>(deg, rowptr, partials, n);
    scan_partials_kernel<<<1, 128, 0, s2>>>(partials, scanBlocks);
    scan_add_kernel<<<(n + 255) / 256, 256, 0, s2>>>(rowptr, partials, fill, n, ne);
    csr_fill_kernel<<<edge2Blocks, 256, 0, s2>>>(ei, ew, ne, fill, epack);
    cudaEventRecord(evJoin, s2);

    // ---- main stream: W prep + layer-1 GEMM overlap the CSR build ----
    prep_w3_kernel<<<152, 256>>>(W1, w1hi, w1lo, W2, w2hi, w2lo,
                                 W3, w3hi, w3lo);
    gemm128_tc_kernel<<<tcBlocks, 256, SMEM_TC>>>(x, w1hi, w1lo, Ah, n);

    // ---- join ----
    cudaStreamWaitEvent(0, evJoin, 0);

    // ---- layer 1 ----
    agg128_kernel<<<nodeWarpBlocks, 256>>>(rowptr, epack, Ah, b1, Bh, n);
    // ---- layer 2 (fp16 x fp16 hi/lo, 2 passes) ----
    gemm128_tc_h16_kernel<<<tcBlocks, 256, SMEM_TCH>>>(Bh, w2hi, w2lo, Ah, n);
    agg128_kernel<<<nodeWarpBlocks, 256>>>(rowptr, epack, Ah, b2, Bh, n);
    // ---- layer 3 (D_OUT = 40, wmma) ----
    gemm40_tc_kernel<<<tcBlocks, 256, SMEM_TC40>>>(Bh, w3hi, w3lo, Ah, n);
    agg40_lsm_kernel<<<nodeWarpBlocks, 256>>>(rowptr, epack, Ah, b3, out, n);
}

// round 17
// speedup vs baseline: 1.5122x; 1.0123x over previous
#include <cuda_runtime.h>
#include <cuda_bf16.h>
#include <cuda_fp16.h>
#include <mma.h>
#include <cstdint>

using namespace nvcuda;

// ---------------------------------------------------------------------------
// AdjGCN: 3-layer GCN forward.
//  - CSR-gather aggregation; CSR built on a forked stream; int2 edge payload.
//  - L1 GEMM: bf16x3 wmma (fp32 X). L2 GEMM: fp16 X x fp16 W hi/lo (2-pass),
//    2 row-tiles per block (W loaded once). L3 GEMM: wmma N=48, 2 row-tiles.
//  - ALL inter-layer tensors fp16; all accumulation fp32.
// ---------------------------------------------------------------------------

#define MAXN 100000
#define MAXNP 100096
#define MAXE 1600000
#define DH   128
#define DO   40
#define NO3  48
#define LDX  136
#define LDW  136
#define LDW3 56
#define LDS  132
#define LDS3 52

__device__ float         g_bufA[(size_t)MAXNP * DH];
__device__ float         g_bufB[(size_t)MAXNP * DH];
__device__ int           g_idx64;
__device__ int           g_rowptr[MAXN + 1];
__device__ int           g_deg[MAXN];
__device__ int           g_fill[MAXN];
__device__ int2          g_epack[MAXE];
__device__ int           g_partials[128];
__device__ __nv_bfloat16 g_w1hi[128 * 128];
__device__ __nv_bfloat16 g_w1lo[128 * 128];
__device__ __half        g_w2hi[128 * 128];
__device__ __half        g_w2lo[128 * 128];
__device__ __half        g_w3hi[128 * NO3];
__device__ __half        g_w3lo[128 * NO3];

// ------------------------------ CSR build ---------------------------------
__global__ void deg_zero_kernel(int* __restrict__ deg, int n,
                                const void* ei, int n_nodes) {
    int i = blockIdx.x * blockDim.x + threadIdx.x;
    if (i < n) deg[i] = 0;
    if (blockIdx.x == 0 && threadIdx.x == 0) {
        const long long* p = (const long long*)ei;
        int ok64 = 1;
        for (int k = 0; k < 32; k++) {
            long long v = p[k];
            if (v < 0 || v >= n_nodes) { ok64 = 0; break; }
        }
        g_idx64 = ok64;
    }
}

__global__ void deg_count_kernel(const void* __restrict__ ei, int ne,
                                 int* __restrict__ deg) {
    int e = (blockIdx.x * blockDim.x + threadIdx.x) * 2;
    if (e >= ne) return;
    int d0, d1 = -1;
    if (g_idx64) {
        const long long* p = (const long long*)ei + ne;
        if (e + 1 < ne) {
            longlong2 v = *(const longlong2*)(p + e);
            d0 = (int)v.x; d1 = (int)v.y;
        } else d0 = (int)p[e];
    } else {
        const int* p = (const int*)ei + ne;
        if (e + 1 < ne) {
            int2 v = *(const int2*)(p + e);
            d0 = v.x; d1 = v.y;
        } else d0 = p[e];
    }
    atomicAdd(&deg[d0], 1);
    if (d1 >= 0) atomicAdd(&deg[d1], 1);
}

__global__ void scan_block_kernel(const int* __restrict__ deg,
                                  int* __restrict__ rowptr,
                                  int* __restrict__ partials, int n) {
    __shared__ int sm[1024];
    const int tid = threadIdx.x;
    int i = blockIdx.x * 1024 + tid;
    int v = (i < n) ? deg[i] : 0;
    sm[tid] = v;
    __syncthreads();
#pragma unroll
    for (int o = 1; o < 1024; o <<= 1) {
        int t = (tid >= o) ? sm[tid - o] : 0;
        __syncthreads();
        sm[tid] += t;
        __syncthreads();
    }
    if (i < n) rowptr[i] = sm[tid] - v;
    if (tid == 1023) partials[blockIdx.x] = sm[1023];
}

__global__ void scan_partials_kernel(int* __restrict__ partials, int nb) {
    __shared__ int sm[128];
    const int tid = threadIdx.x;
    int v = (tid < nb) ? partials[tid] : 0;
    sm[tid] = v;
    __syncthreads();
#pragma unroll
    for (int o = 1; o < 128; o <<= 1) {
        int t = (tid >= o) ? sm[tid - o] : 0;
        __syncthreads();
        sm[tid] += t;
        __syncthreads();
    }
    if (tid < nb) partials[tid] = sm[tid] - v;
}

__global__ void scan_add_kernel(int* __restrict__ rowptr,
                                const int* __restrict__ partials,
                                int* __restrict__ fill, int n, int ne) {
    int i = blockIdx.x * blockDim.x + threadIdx.x;
    if (i < n) {
        int v = rowptr[i] + partials[i >> 10];
        rowptr[i] = v;
        fill[i] = v;
    }
    if (i == 0) rowptr[n] = ne;
}

__global__ void csr_fill_kernel(const void* __restrict__ ei,
                                const float* __restrict__ ew, int ne,
                                int* __restrict__ fill,
                                int2* __restrict__ epack) {
    int e = (blockIdx.x * blockDim.x + threadIdx.x) * 2;
    if (e >= ne) return;
    int s0, d0, s1 = -1, d1 = -1;
    float w0, w1 = 0.f;
    if (g_idx64) {
        const long long* ps = (const long long*)ei;
        const long long* pd = ps + ne;
        if (e + 1 < ne) {
            longlong2 sv = *(const longlong2*)(ps + e);
            longlong2 dv = *(const longlong2*)(pd + e);
            float2 wv = *(const float2*)(ew + e);
            s0 = (int)sv.x; s1 = (int)sv.y;
            d0 = (int)dv.x; d1 = (int)dv.y;
            w0 = wv.x; w1 = wv.y;
        } else { s0 = (int)ps[e]; d0 = (int)pd[e]; w0 = ew[e]; }
    } else {
        const int* ps = (const int*)ei;
        const int* pd = ps + ne;
        if (e + 1 < ne) {
            int2 sv = *(const int2*)(ps + e);
            int2 dv = *(const int2*)(pd + e);
            float2 wv = *(const float2*)(ew + e);
            s0 = sv.x; s1 = sv.y; d0 = dv.x; d1 = dv.y;
            w0 = wv.x; w1 = wv.y;
        } else { s0 = ps[e]; d0 = pd[e]; w0 = ew[e]; }
    }
    int p0 = atomicAdd(&fill[d0], 1);
    epack[p0] = make_int2(s0, __float_as_int(w0));
    if (s1 >= 0) {
        int p1 = atomicAdd(&fill[d1], 1);
        epack[p1] = make_int2(s1, __float_as_int(w1));
    }
}

// ---- W prep: W1 -> bf16 hi/lo; W2 -> fp16 hi/lo; W3 -> fp16 hi/lo (N=48) --
__global__ void prep_w3_kernel(const float* __restrict__ Wa,
                               __nv_bfloat16* __restrict__ ahi,
                               __nv_bfloat16* __restrict__ alo,
                               const float* __restrict__ Wb,
                               __half* __restrict__ bhi,
                               __half* __restrict__ blo,
                               const float* __restrict__ Wc,
                               __half* __restrict__ chi,
                               __half* __restrict__ clo) {
    int i = blockIdx.x * blockDim.x + threadIdx.x;
    if (i < 128 * 128) {
        float w = Wa[i];
        __nv_bfloat16 h = __float2bfloat16_rn(w);
        ahi[i] = h;
        alo[i] = __float2bfloat16_rn(w - __bfloat162float(h));
    } else if (i < 2 * 128 * 128) {
        int k = i - 128 * 128;
        float w = Wb[k];
        __half h = __float2half_rn(w);
        bhi[k] = h;
        blo[k] = __float2half_rn(w - __half2float(h));
    } else if (i < 2 * 128 * 128 + 128 * NO3) {
        int k = i - 2 * 128 * 128;
        int row = k / NO3, col = k % NO3;
        float w = (col < DO) ? Wc[row * DO + col] : 0.f;
        __half h = __float2half_rn(w);
        chi[k] = h;
        clo[k] = __float2half_rn(w - __half2float(h));
    }
}

// ------------------ bf16 hi/lo packing helpers -----------------------------
__device__ __forceinline__ uint64_t pack4_hi(float a, float b, float c, float d) {
    __nv_bfloat162 p0 = __floats2bfloat162_rn(a, b);
    __nv_bfloat162 p1 = __floats2bfloat162_rn(c, d);
    return (uint64_t)(*(uint32_t*)&p0) | ((uint64_t)(*(uint32_t*)&p1) << 32);
}
__device__ __forceinline__ uint64_t pack4_lo(float a, float b, float c, float d) {
    float ah = __bfloat162float(__float2bfloat16_rn(a));
    float bh = __bfloat162float(__float2bfloat16_rn(b));
    float ch = __bfloat162float(__float2bfloat16_rn(c));
    float dh = __bfloat162float(__float2bfloat16_rn(d));
    __nv_bfloat162 p0 = __floats2bfloat162_rn(a - ah, b - bh);
    __nv_bfloat162 p1 = __floats2bfloat162_rn(c - ch, d - dh);
    return (uint64_t)(*(uint32_t*)&p0) | ((uint64_t)(*(uint32_t*)&p1) << 32);
}

// ---------- layer-1 GEMM: fp32 X -> bf16x3 wmma -> fp16 H ------------------
__global__ void gemm128_tc_kernel(const float* __restrict__ X,
                                  const __nv_bfloat16* __restrict__ Whi,
                                  const __nv_bfloat16* __restrict__ Wlo,
                                  __half* __restrict__ Yh, int nrows) {
    extern __shared__ char smem[];
    __nv_bfloat16* xhi = (__nv_bfloat16*)smem;
    __nv_bfloat16* xlo = xhi + 64 * LDX;
    __nv_bfloat16* wh  = xlo + 64 * LDX;
    __nv_bfloat16* wl  = wh + 128 * LDW;
    const int tid = threadIdx.x;
    const int row0 = blockIdx.x * 64;

    {
        const float4* X4 = (const float4*)X;
#pragma unroll
        for (int i = tid; i < 64 * 32; i += 256) {
            int r = i >> 5, kq = i & 31;
            float4 v = (row0 + r < nrows)
                           ? X4[(size_t)(row0 + r) * 32 + kq]
                           : make_float4(0.f, 0.f, 0.f, 0.f);
            *(uint64_t*)&xhi[r * LDX + kq * 4] = pack4_hi(v.x, v.y, v.z, v.w);
            *(uint64_t*)&xlo[r * LDX + kq * 4] = pack4_lo(v.x, v.y, v.z, v.w);
        }
    }
    {
        const int4* h4 = (const int4*)Whi;
        const int4* l4 = (const int4*)Wlo;
#pragma unroll
        for (int i = tid; i < 2048; i += 256) {
            int k = i >> 4, seg = i & 15;
            *(int4*)&wh[k * LDW + seg * 8] = h4[i];
            *(int4*)&wl[k * LDW + seg * 8] = l4[i];
        }
    }
    __syncthreads();

    const int w  = tid >> 5;
    const int wr = w >> 2;
    const int wc = w & 3;

    wmma::fragment<wmma::accumulator, 16, 16, 16, float> acc[2][2];
#pragma unroll
    for (int i = 0; i < 2; i++)
#pragma unroll
        for (int j = 0; j < 2; j++) wmma::fill_fragment(acc[i][j], 0.f);

#pragma unroll
    for (int ks = 0; ks < 8; ks++) {
        const int k0 = ks * 16;
        wmma::fragment<wmma::matrix_a, 16, 16, 16, __nv_bfloat16,
                       wmma::row_major> ah[2], al[2];
        wmma::fragment<wmma::matrix_b, 16, 16, 16, __nv_bfloat16,
                       wmma::row_major> bh[2], bl[2];
#pragma unroll
        for (int i = 0; i < 2; i++) {
            wmma::load_matrix_sync(ah[i], &xhi[(wr * 32 + i * 16) * LDX + k0], LDX);
            wmma::load_matrix_sync(al[i], &xlo[(wr * 32 + i * 16) * LDX + k0], LDX);
        }
#pragma unroll
        for (int j = 0; j < 2; j++) {
            wmma::load_matrix_sync(bh[j], &wh[k0 * LDW + wc * 32 + j * 16], LDW);
            wmma::load_matrix_sync(bl[j], &wl[k0 * LDW + wc * 32 + j * 16], LDW);
        }
#pragma unroll
        for (int i = 0; i < 2; i++)
#pragma unroll
            for (int j = 0; j < 2; j++) {
                wmma::mma_sync(acc[i][j], ah[i], bh[j], acc[i][j]);
                wmma::mma_sync(acc[i][j], ah[i], bl[j], acc[i][j]);
                wmma::mma_sync(acc[i][j], al[i], bh[j], acc[i][j]);
            }
    }

    __syncthreads();
    float* stage = (float*)smem;
#pragma unroll
    for (int i = 0; i < 2; i++)
#pragma unroll
        for (int j = 0; j < 2; j++) {
            wmma::store_matrix_sync(&stage[(wr * 32 + i * 16) * LDS
                                           + wc * 32 + j * 16],
                                    acc[i][j], LDS, wmma::mem_row_major);
        }
    __syncthreads();
    __half2* Y2 = (__half2*)Yh;
#pragma unroll
    for (int i = tid; i < 64 * 64; i += 256) {
        int r = i >> 6, c2 = i & 63;
        float a = stage[r * LDS + 2 * c2];
        float b = stage[r * LDS + 2 * c2 + 1];
        Y2[(size_t)(row0 + r) * 64 + c2] = __floats2half2_rn(a, b);
    }
}

// ---- layer-2 GEMM: fp16 X x fp16 W hi/lo, 2 passes, 2 row-tiles/block -----
// W loaded once; epilogue stages 32 rows at a time in the dead X region.
__global__ void gemm128_tc_h16_kernel(const __half* __restrict__ X16,
                                      const __half* __restrict__ Whi,
                                      const __half* __restrict__ Wlo,
                                      __half* __restrict__ Yh, int nrows) {
    extern __shared__ char smem[];
    __half* xs = (__half*)smem;          // 64 * LDX halves (17408 B)
    __half* wh = xs + 64 * LDX;          // 128 * LDW
    __half* wl = wh + 128 * LDW;
    const int tid = threadIdx.x;
    const int w  = tid >> 5;
    const int wr = w >> 2;
    const int wc = w & 3;

    {
        const int4* h4 = (const int4*)Whi;
        const int4* l4 = (const int4*)Wlo;
#pragma unroll
        for (int i = tid; i < 2048; i += 256) {
            int k = i >> 4, seg = i & 15;
            *(int4*)&wh[k * LDW + seg * 8] = h4[i];
            *(int4*)&wl[k * LDW + seg * 8] = l4[i];
        }
    }

    const uint2* X2 = (const uint2*)X16;
    __half2* Y2 = (__half2*)Yh;
    float* stage32 = (float*)xs;   // 32*LDS*4 = 16896 B <= 17408 B

#pragma unroll
    for (int t = 0; t < 2; t++) {
        const int row0 = blockIdx.x * 128 + t * 64;
        if (row0 >= nrows && t == 1) break;
        __syncthreads();   // protect xs (stage of prev iter) before reload
#pragma unroll
        for (int i = tid; i < 64 * 32; i += 256) {
            int r = i >> 5, kq = i & 31;
            uint2 u = make_uint2(0u, 0u);
            if (row0 + r < nrows) u = X2[(size_t)(row0 + r) * 32 + kq];
            *(uint2*)&xs[r * LDX + kq * 4] = u;
        }
        __syncthreads();

        wmma::fragment<wmma::accumulator, 16, 16, 16, float> acc[2][2];
#pragma unroll
        for (int i = 0; i < 2; i++)
#pragma unroll
            for (int j = 0; j < 2; j++) wmma::fill_fragment(acc[i][j], 0.f);

#pragma unroll
        for (int ks = 0; ks < 8; ks++) {
            const int k0 = ks * 16;
            wmma::fragment<wmma::matrix_a, 16, 16, 16, __half,
                           wmma::row_major> a[2];
            wmma::fragment<wmma::matrix_b, 16, 16, 16, __half,
                           wmma::row_major> bh[2], bl[2];
#pragma unroll
            for (int i = 0; i < 2; i++)
                wmma::load_matrix_sync(a[i], &xs[(wr * 32 + i * 16) * LDX + k0], LDX);
#pragma unroll
            for (int j = 0; j < 2; j++) {
                wmma::load_matrix_sync(bh[j], &wh[k0 * LDW + wc * 32 + j * 16], LDW);
                wmma::load_matrix_sync(bl[j], &wl[k0 * LDW + wc * 32 + j * 16], LDW);
            }
#pragma unroll
            for (int i = 0; i < 2; i++)
#pragma unroll
                for (int j = 0; j < 2; j++) {
                    wmma::mma_sync(acc[i][j], a[i], bh[j], acc[i][j]);
                    wmma::mma_sync(acc[i][j], a[i], bl[j], acc[i][j]);
                }
        }

        // Staged epilogue: 32 rows (one wr half) at a time through xs region.
#pragma unroll
        for (int half = 0; half < 2; half++) {
            __syncthreads();
            if (wr == half) {
#pragma unroll
                for (int i = 0; i < 2; i++)
#pragma unroll
                    for (int j = 0; j < 2; j++)
                        wmma::store_matrix_sync(
                            &stage32[(i * 16) * LDS + wc * 32 + j * 16],
                            acc[i][j], LDS, wmma::mem_row_major);
            }
            __syncthreads();
#pragma unroll
            for (int i = tid; i < 32 * 64; i += 256) {
                int r = i >> 6, c2 = i & 63;
                float a = stage32[r * LDS + 2 * c2];
                float b = stage32[r * LDS + 2 * c2 + 1];
                Y2[(size_t)(row0 + half * 32 + r) * 64 + c2] =
                    __floats2half2_rn(a, b);
            }
        }
    }
}

// ---- layer-3 GEMM (D_OUT=40): fp16 X x fp16 W3 hi/lo, 2 row-tiles/block ---
__global__ void gemm40_tc_kernel(const __half* __restrict__ X16,
                                 const __half* __restrict__ Whi,
                                 const __half* __restrict__ Wlo,
                                 __half* __restrict__ Yh, int nrows) {
    extern __shared__ char smem[];
    __half* xs = (__half*)smem;          // 64 * LDX halves (17408 B)
    __half* wh = xs + 64 * LDX;          // 128 * LDW3
    __half* wl = wh + 128 * LDW3;
    const int tid = threadIdx.x;
    const int w  = tid >> 5;
    const int wr = w & 1;
    const int wc = w >> 1;      // active wc<3

    {
        const int4* h4 = (const int4*)Whi;   // 128*48 halves = 768 int4
        const int4* l4 = (const int4*)Wlo;
#pragma unroll
        for (int i = tid; i < 768; i += 256) {
            int k = i / 6, seg = i % 6;
            *(int4*)&wh[k * LDW3 + seg * 8] = h4[i];
            *(int4*)&wl[k * LDW3 + seg * 8] = l4[i];
        }
    }

    const uint2* X2 = (const uint2*)X16;
    __half2* Y2 = (__half2*)Yh;
    float* stage = (float*)xs;    // 64*LDS3*4 = 13312 B <= 17408 B

#pragma unroll
    for (int t = 0; t < 2; t++) {
        const int row0 = blockIdx.x * 128 + t * 64;
        if (row0 >= nrows && t == 1) break;
        __syncthreads();
#pragma unroll
        for (int i = tid; i < 64 * 32; i += 256) {
            int r = i >> 5, kq = i & 31;
            uint2 u = make_uint2(0u, 0u);
            if (row0 + r < nrows) u = X2[(size_t)(row0 + r) * 32 + kq];
            *(uint2*)&xs[r * LDX + kq * 4] = u;
        }
        __syncthreads();

        wmma::fragment<wmma::accumulator, 16, 16, 16, float> acc[2];
#pragma unroll
        for (int i = 0; i < 2; i++) wmma::fill_fragment(acc[i], 0.f);

        if (wc < 3) {
#pragma unroll
            for (int ks = 0; ks < 8; ks++) {
                const int k0 = ks * 16;
                wmma::fragment<wmma::matrix_a, 16, 16, 16, __half,
                               wmma::row_major> a[2];
                wmma::fragment<wmma::matrix_b, 16, 16, 16, __half,
                               wmma::row_major> bh, bl;
#pragma unroll
                for (int i = 0; i < 2; i++)
                    wmma::load_matrix_sync(a[i],
                        &xs[(wr * 32 + i * 16) * LDX + k0], LDX);
                wmma::load_matrix_sync(bh, &wh[k0 * LDW3 + wc * 16], LDW3);
                wmma::load_matrix_sync(bl, &wl[k0 * LDW3 + wc * 16], LDW3);
#pragma unroll
                for (int i = 0; i < 2; i++) {
                    wmma::mma_sync(acc[i], a[i], bh, acc[i]);
                    wmma::mma_sync(acc[i], a[i], bl, acc[i]);
                }
            }
        }
        __syncthreads();   // xs (X data) dead; reuse as stage
        if (wc < 3) {
#pragma unroll
            for (int i = 0; i < 2; i++)
                wmma::store_matrix_sync(
                    &stage[(wr * 32 + i * 16) * LDS3 + wc * 16],
                    acc[i], LDS3, wmma::mem_row_major);
        }
        __syncthreads();
#pragma unroll
        for (int i = tid; i < 64 * 20; i += 256) {
            int r = i / 20, c2 = i % 20;
            float a = stage[r * LDS3 + 2 * c2];
            float b = stage[r * LDS3 + 2 * c2 + 1];
            Y2[(size_t)(row0 + r) * 20 + c2] = __floats2half2_rn(a, b);
        }
    }
}

// ----------------------- CSR gather aggregation ----------------------------
__global__ void agg128_kernel(const int* __restrict__ rowptr,
                              const int2* __restrict__ epack,
                              const __half* __restrict__ H,
                              const float* __restrict__ bias,
                              __half* __restrict__ Y, int n) {
    int node = blockIdx.x * 8 + (threadIdx.x >> 5);
    if (node >= n) return;
    const int lane = threadIdx.x & 31;
    int beg = rowptr[node];
    int end = rowptr[node + 1];

    float4 acc = make_float4(0.f, 0.f, 0.f, 0.f);
    int j = beg;
    for (; j + 7 < end; j += 8) {
        int2 ed[8];
        uint2 u[8];
#pragma unroll
        for (int q = 0; q < 8; q++) ed[q] = epack[j + q];
#pragma unroll
        for (int q = 0; q < 8; q++)
            u[q] = ((const uint2*)(H + (size_t)ed[q].x * 128))[lane];
#pragma unroll
        for (int q = 0; q < 8; q++) {
            float w = __int_as_float(ed[q].y);
            float2 a = __half22float2(*(__half2*)&u[q].x);
            float2 b = __half22float2(*(__half2*)&u[q].y);
            acc.x += a.x * w; acc.y += a.y * w;
            acc.z += b.x * w; acc.w += b.y * w;
        }
    }
    for (; j < end; j++) {
        int2 e = epack[j];
        float w = __int_as_float(e.y);
        uint2 u = ((const uint2*)(H + (size_t)e.x * 128))[lane];
        float2 a = __half22float2(*(__half2*)&u.x);
        float2 b = __half22float2(*(__half2*)&u.y);
        acc.x += a.x * w; acc.y += a.y * w;
        acc.z += b.x * w; acc.w += b.y * w;
    }

    float4 b4 = ((const float4*)bias)[lane];
    acc.x = fmaxf(acc.x + b4.x, 0.f);
    acc.y = fmaxf(acc.y + b4.y, 0.f);
    acc.z = fmaxf(acc.z + b4.z, 0.f);
    acc.w = fmaxf(acc.w + b4.w, 0.f);
    __half2 h0 = __floats2half2_rn(acc.x, acc.y);
    __half2 h1 = __floats2half2_rn(acc.z, acc.w);
    uint2 o;
    o.x = *(uint32_t*)&h0;
    o.y = *(uint32_t*)&h1;
    ((uint2*)(Y + (size_t)node * 128))[lane] = o;
}

// D=40 gather (fp16 H) + bias + log_softmax, one warp per node, unroll 8.
__global__ void agg40_lsm_kernel(const int* __restrict__ rowptr,
                                 const int2* __restrict__ epack,
                                 const __half* __restrict__ H,
                                 const float* __restrict__ b,
                                 float* __restrict__ out, int n) {
    int node = blockIdx.x * 8 + (threadIdx.x >> 5);
    if (node >= n) return;
    const int lane = threadIdx.x & 31;
    int beg = rowptr[node];
    int end = rowptr[node + 1];

    float a0 = 0.f, a1 = 0.f;
    int j = beg;
    for (; j + 7 < end; j += 8) {
        int2 ed[8];
#pragma unroll
        for (int q = 0; q < 8; q++) ed[q] = epack[j + q];
        __half v0[8], v1[8];
#pragma unroll
        for (int q = 0; q < 8; q++) {
            const __half* hs = H + (size_t)ed[q].x * DO;
            v0[q] = hs[lane];
            v1[q] = (lane < 8) ? hs[32 + lane] : __half(0.f);
        }
#pragma unroll
        for (int q = 0; q < 8; q++) {
            float w = __int_as_float(ed[q].y);
            a0 += __half2float(v0[q]) * w;
            a1 += __half2float(v1[q]) * w;
        }
    }
    for (; j < end; j++) {
        int2 e = epack[j];
        float w = __int_as_float(e.y);
        const __half* hs = H + (size_t)e.x * DO;
        a0 += __half2float(hs[lane]) * w;
        if (lane < 8) a1 += __half2float(hs[32 + lane]) * w;
    }

    float v0 = a0 + b[lane];
    float v1 = (lane < 8) ? (a1 + b[32 + lane]) : -1e30f;

    float m = fmaxf(v0, v1);
#pragma unroll
    for (int o = 16; o; o >>= 1) m = fmaxf(m, __shfl_xor_sync(0xffffffffu, m, o));

    float sum = __expf(v0 - m) + ((lane < 8) ? __expf(v1 - m) : 0.f);
#pragma unroll
    for (int o = 16; o; o >>= 1) sum += __shfl_xor_sync(0xffffffffu, sum, o);

    float lse = m + __logf(sum);
    out[(size_t)node * DO + lane] = v0 - lse;
    if (lane < 8) out[(size_t)node * DO + 32 + lane] = v1 - lse;
}

// ---------------------------------------------------------------------------
extern "C" void kernel_launch(void* const* d_in, const int* in_sizes, int n_in,
                              void* d_out, int out_size) {
    const float* x  = (const float*)d_in[0];
    const void*  ei = d_in[1];
    const float* ew = (const float*)d_in[2];
    const float* W1 = (const float*)d_in[3];
    const float* b1 = (const float*)d_in[4];
    const float* W2 = (const float*)d_in[5];
    const float* b2 = (const float*)d_in[6];
    const float* W3 = (const float*)d_in[7];
    const float* b3 = (const float*)d_in[8];
    float* out = (float*)d_out;

    const int n  = in_sizes[0] / DH;
    int ne = in_sizes[1] / 2;
    if (ne > MAXE) ne = MAXE;
    (void)n_in; (void)out_size;

    float *A, *B;
    int *rowptr, *deg, *fill, *partials;
    int2* epack;
    __nv_bfloat16 *w1hi, *w1lo;
    __half *w2hi, *w2lo, *w3hi, *w3lo;
    cudaGetSymbolAddress((void**)&A, g_bufA);
    cudaGetSymbolAddress((void**)&B, g_bufB);
    cudaGetSymbolAddress((void**)&rowptr, g_rowptr);
    cudaGetSymbolAddress((void**)&deg, g_deg);
    cudaGetSymbolAddress((void**)&fill, g_fill);
    cudaGetSymbolAddress((void**)&epack, g_epack);
    cudaGetSymbolAddress((void**)&partials, g_partials);
    cudaGetSymbolAddress((void**)&w1hi, g_w1hi);
    cudaGetSymbolAddress((void**)&w1lo, g_w1lo);
    cudaGetSymbolAddress((void**)&w2hi, g_w2hi);
    cudaGetSymbolAddress((void**)&w2lo, g_w2lo);
    cudaGetSymbolAddress((void**)&w3hi, g_w3hi);
    cudaGetSymbolAddress((void**)&w3lo, g_w3lo);

    __half* Ah = (__half*)A;
    __half* Bh = (__half*)B;

    const int SMEM_TC   = (2 * 64 * LDX + 2 * 128 * LDW) * (int)sizeof(__nv_bfloat16);
    const int SMEM_TCH  = (64 * LDX + 2 * 128 * LDW) * (int)sizeof(__half);
    const int SMEM_TC40 = (64 * LDX + 2 * 128 * LDW3) * (int)sizeof(__half);
    cudaFuncSetAttribute(gemm128_tc_kernel,
                         cudaFuncAttributeMaxDynamicSharedMemorySize, SMEM_TC);
    cudaFuncSetAttribute(gemm128_tc_h16_kernel,
                         cudaFuncAttributeMaxDynamicSharedMemorySize, SMEM_TCH);
    cudaFuncSetAttribute(gemm40_tc_kernel,
                         cudaFuncAttributeMaxDynamicSharedMemorySize, SMEM_TC40);

    const int tcBlocks       = (n + 63) / 64;
    const int tcBlocks2      = (n + 127) / 128;
    const int nodeWarpBlocks = (n + 7) / 8;
    const int scanBlocks     = (n + 1023) / 1024;
    const int edge2Blocks    = ((ne + 1) / 2 + 255) / 256;

    static cudaStream_t s2 = nullptr;
    static cudaEvent_t evFork = nullptr, evJoin = nullptr;
    if (s2 == nullptr) {
        cudaStreamCreateWithFlags(&s2, cudaStreamNonBlocking);
        cudaEventCreateWithFlags(&evFork, cudaEventDisableTiming);
        cudaEventCreateWithFlags(&evJoin, cudaEventDisableTiming);
    }

    // ---- fork: CSR build on side stream ----
    cudaEventRecord(evFork, 0);
    cudaStreamWaitEvent(s2, evFork, 0);
    deg_zero_kernel<<<(n + 255) / 256, 256, 0, s2>>>(deg, n, ei, n);
    deg_count_kernel<<<edge2Blocks, 256, 0, s2>>>(ei, ne, deg);
    scan_block_kernel<<<scanBlocks, 1024, 0, s2>>>(deg, rowptr, partials, n);
    scan_partials_kernel<<<1, 128, 0, s2>>>(partials, scanBlocks);
    scan_add_kernel<<<(n + 255) / 256, 256, 0, s2>>>(rowptr, partials, fill, n, ne);
    csr_fill_kernel<<<edge2Blocks, 256, 0, s2>>>(ei, ew, ne, fill, epack);
    cudaEventRecord(evJoin, s2);

    // ---- main stream: W prep + layer-1 GEMM overlap the CSR build ----
    prep_w3_kernel<<<152, 256>>>(W1, w1hi, w1lo, W2, w2hi, w2lo,
                                 W3, w3hi, w3lo);
    gemm128_tc_kernel<<<tcBlocks, 256, SMEM_TC>>>(x, w1hi, w1lo, Ah, n);

    // ---- join ----
    cudaStreamWaitEvent(0, evJoin, 0);

    // ---- layer 1 ----
    agg128_kernel<<<nodeWarpBlocks, 256>>>(rowptr, epack, Ah, b1, Bh, n);
    // ---- layer 2 (fp16 x fp16 hi/lo, 2 passes, 2 tiles/block) ----
    gemm128_tc_h16_kernel<<<tcBlocks2, 256, SMEM_TCH>>>(Bh, w2hi, w2lo, Ah, n);
    agg128_kernel<<<nodeWarpBlocks, 256>>>(rowptr, epack, Ah, b2, Bh, n);
    // ---- layer 3 (D_OUT = 40, wmma, 2 tiles/block) ----
    gemm40_tc_kernel<<<tcBlocks2, 256, SMEM_TC40>>>(Bh, w3hi, w3lo, Ah, n);
    agg40_lsm_kernel<<<nodeWarpBlocks, 256>>>(rowptr, epack, Ah, b3, out, n);
}